// round 4
// baseline (speedup 1.0000x reference)
#include <cuda_runtime.h>
#include <cuda_bf16.h>
#include <math.h>

#define MSZ   1024
#define M2    (MSZ * MSZ)
#define NPER  128
#define DDIM  64
#define NBAT  2048
#define NIDX  (NBAT * NPER)          // 262144
#define SIGN  (NBAT * NPER * DDIM)   // 16777216

// Scratch: 6 matrix buffers of 4MB each + index scratch
__device__ float g_scratch[6 * M2];
__device__ int g_rows[NIDX];
__device__ unsigned int g_odd_or;

// ---------------------------------------------------------------------------
// f32x2 packed helpers (FFMA2 — only reachable via PTX)
// ---------------------------------------------------------------------------
__device__ __forceinline__ unsigned long long pack2(float x, float y) {
    unsigned long long r;
    asm("mov.b64 %0, {%1, %2};" : "=l"(r) : "f"(x), "f"(y));
    return r;
}
__device__ __forceinline__ void fma2(unsigned long long& d,
                                     unsigned long long a,
                                     unsigned long long b) {
    asm("fma.rn.f32x2 %0, %1, %2, %0;" : "+l"(d) : "l"(a), "l"(b));
}
__device__ __forceinline__ void unpack2(unsigned long long v, float& lo, float& hi) {
    asm("mov.b64 {%0, %1}, %2;" : "=f"(lo), "=f"(hi) : "l"(v));
}

// ---------------------------------------------------------------------------
// Index dtype detection + conversion.
// If the buffer holds int64 (little-endian, values < 2^31), every odd int32
// word is 0. If it holds int32 indices, odd words are random in 0..1023.
// Only touches the first NIDX int32 words = 1MB = min footprint either way.
// ---------------------------------------------------------------------------
__global__ void idx_detect_kernel(const unsigned int* __restrict__ v32) {
    __shared__ unsigned int s[256];
    unsigned int o = 0;
    // odd words within first NIDX int32s: indices 1,3,...,NIDX-1
    for (int i = threadIdx.x; i < NIDX / 2; i += 256)
        o |= v32[2 * i + 1];
    s[threadIdx.x] = o;
    __syncthreads();
    for (int d = 128; d > 0; d >>= 1) {
        if (threadIdx.x < d) s[threadIdx.x] |= s[threadIdx.x + d];
        __syncthreads();
    }
    if (threadIdx.x == 0) g_odd_or = s[0];
}

__global__ void idx_convert_kernel(const void* __restrict__ raw) {
    int i = blockIdx.x * blockDim.x + threadIdx.x;
    if (i >= NIDX) return;
    if (g_odd_or == 0u) {
        // int64 layout
        g_rows[i] = (int)((const long long*)raw)[i];
    } else {
        // int32 layout
        g_rows[i] = ((const int*)raw)[i];
    }
}

// ---------------------------------------------------------------------------
// Transpose: T = A^T
// ---------------------------------------------------------------------------
__global__ void transpose_kernel(const float* __restrict__ A, float* __restrict__ T) {
    __shared__ float tile[32][33];
    int x = blockIdx.x * 32 + threadIdx.x;
    int y = blockIdx.y * 32 + threadIdx.y;
#pragma unroll
    for (int j = 0; j < 32; j += 8)
        tile[threadIdx.y + j][threadIdx.x] = A[(y + j) * MSZ + x];
    __syncthreads();
    x = blockIdx.y * 32 + threadIdx.x;
    y = blockIdx.x * 32 + threadIdx.y;
#pragma unroll
    for (int j = 0; j < 32; j += 8)
        T[(y + j) * MSZ + x] = tile[threadIdx.x][threadIdx.y + j];
}

// ---------------------------------------------------------------------------
// diag add: M += I (in place)
// ---------------------------------------------------------------------------
__global__ void diag_add_kernel(float* M) {
    int i = blockIdx.x * blockDim.x + threadIdx.x;
    if (i < MSZ) M[i * MSZ + i] += 1.0f;
}

// ---------------------------------------------------------------------------
// SGEMM: D = A*B (+ C).  1024x1024 row-major.
// BM=128, BN=64, BK=16, 256 threads, 8x4 microtile, f32x2 packed FMA.
// ---------------------------------------------------------------------------
#define BM 128
#define BN 64
#define BK 16
__global__ void __launch_bounds__(256) gemm_kernel(
    const float* __restrict__ A, const float* __restrict__ B,
    const float* __restrict__ C, float* __restrict__ Dm) {
    __shared__ __align__(16) float As[BK][BM];   // transposed A tile [k][m]
    __shared__ __align__(16) float Bs[BK][BN];   // [k][n]

    const int t  = threadIdx.x;
    const int tx = t % 16;
    const int ty = t / 16;
    const int row0 = blockIdx.y * BM;
    const int col0 = blockIdx.x * BN;

    const int la_row = t & 127;
    const int la_k   = (t >> 7) * 8;
    const int lb_k = t / 16;
    const int lb_n = (t % 16) * 4;

    unsigned long long acc[4][4];
#pragma unroll
    for (int i = 0; i < 4; i++)
#pragma unroll
        for (int j = 0; j < 4; j++) acc[i][j] = 0ull;

    for (int k0 = 0; k0 < MSZ; k0 += BK) {
        float4 av0 = *(const float4*)&A[(size_t)(row0 + la_row) * MSZ + k0 + la_k];
        float4 av1 = *(const float4*)&A[(size_t)(row0 + la_row) * MSZ + k0 + la_k + 4];
        float4 bv  = *(const float4*)&B[(size_t)(k0 + lb_k) * MSZ + col0 + lb_n];
        __syncthreads();
        As[la_k + 0][la_row] = av0.x;
        As[la_k + 1][la_row] = av0.y;
        As[la_k + 2][la_row] = av0.z;
        As[la_k + 3][la_row] = av0.w;
        As[la_k + 4][la_row] = av1.x;
        As[la_k + 5][la_row] = av1.y;
        As[la_k + 6][la_row] = av1.z;
        As[la_k + 7][la_row] = av1.w;
        *(float4*)&Bs[lb_k][lb_n] = bv;
        __syncthreads();

#pragma unroll
        for (int k = 0; k < BK; k++) {
            float4 a0 = *(const float4*)&As[k][ty * 8];
            float4 a1 = *(const float4*)&As[k][ty * 8 + 4];
            float4 b4 = *(const float4*)&Bs[k][tx * 4];
            unsigned long long a2[4], bb[4];
            a2[0] = pack2(a0.x, a0.y);
            a2[1] = pack2(a0.z, a0.w);
            a2[2] = pack2(a1.x, a1.y);
            a2[3] = pack2(a1.z, a1.w);
            bb[0] = pack2(b4.x, b4.x);
            bb[1] = pack2(b4.y, b4.y);
            bb[2] = pack2(b4.z, b4.z);
            bb[3] = pack2(b4.w, b4.w);
#pragma unroll
            for (int i = 0; i < 4; i++)
#pragma unroll
                for (int j = 0; j < 4; j++)
                    fma2(acc[i][j], a2[i], bb[j]);
        }
    }

#pragma unroll
    for (int i = 0; i < 4; i++) {
        float lo[4], hi[4];
#pragma unroll
        for (int j = 0; j < 4; j++) unpack2(acc[i][j], lo[j], hi[j]);
        int r0 = row0 + ty * 8 + 2 * i;
        float4 v0 = make_float4(lo[0], lo[1], lo[2], lo[3]);
        float4 v1 = make_float4(hi[0], hi[1], hi[2], hi[3]);
        if (C) {
            float4 c0 = *(const float4*)&C[(size_t)r0 * MSZ + col0 + tx * 4];
            float4 c1 = *(const float4*)&C[(size_t)(r0 + 1) * MSZ + col0 + tx * 4];
            v0.x += c0.x; v0.y += c0.y; v0.z += c0.z; v0.w += c0.w;
            v1.x += c1.x; v1.y += c1.y; v1.z += c1.z; v1.w += c1.w;
        }
        *(float4*)&Dm[(size_t)r0 * MSZ + col0 + tx * 4] = v0;
        *(float4*)&Dm[(size_t)(r0 + 1) * MSZ + col0 + tx * 4] = v1;
    }
}

// ---------------------------------------------------------------------------
// sigma = mu + eps * exp(logstd)
// ---------------------------------------------------------------------------
__global__ void sigma_kernel(const float4* __restrict__ mu,
                             const float4* __restrict__ ls,
                             const float4* __restrict__ ep,
                             float4* __restrict__ out) {
    int i = blockIdx.x * blockDim.x + threadIdx.x;
    float4 m = mu[i], l = ls[i], e = ep[i];
    float4 r;
    r.x = m.x + e.x * expf(l.x);
    r.y = m.y + e.y * expf(l.y);
    r.z = m.z + e.z * expf(l.z);
    r.w = m.w + e.w * expf(l.w);
    out[i] = r;
}

// ---------------------------------------------------------------------------
// z[b] = S[idx[b], :][:, idx[b]] @ sigma[b]   (one CTA per batch)
// ---------------------------------------------------------------------------
#define ZSMEM ((NPER * NPER + NPER * DDIM + NPER) * 4)
__global__ void __launch_bounds__(256) z_kernel(
    const float* __restrict__ S, const float* __restrict__ sigma,
    const int* __restrict__ ridx, float* __restrict__ z) {
    extern __shared__ float smem[];
    float* sub_s = smem;                     // 128*128
    float* sig_s = smem + NPER * NPER;       // 128*64
    int*   rows  = (int*)(sig_s + NPER * DDIM);

    const int b = blockIdx.x;
    const int t = threadIdx.x;

    if (t < NPER) rows[t] = ridx[b * NPER + t];
    {
        const float4* sg = (const float4*)(sigma + (size_t)b * NPER * DDIM);
        float4* ss = (float4*)sig_s;
        for (int i = t; i < NPER * DDIM / 4; i += 256) ss[i] = sg[i];
    }
    __syncthreads();

    {
        const int tj  = t & 127;
        const int ti0 = (t >> 7) * 64;
        const int cj  = rows[tj];
#pragma unroll 4
        for (int ii = 0; ii < 64; ii++) {
            int i = ti0 + ii;
            sub_s[i * NPER + tj] = S[(size_t)rows[i] * MSZ + cj];
        }
    }
    __syncthreads();

    const int d4 = t & 15;
    const int ig = t >> 4;
    float4 acc[8];
#pragma unroll
    for (int r = 0; r < 8; r++) acc[r] = make_float4(0.f, 0.f, 0.f, 0.f);

    const float4* sig4 = (const float4*)sig_s;
    for (int j = 0; j < NPER; j++) {
        float4 sv = sig4[j * (DDIM / 4) + d4];
#pragma unroll
        for (int r = 0; r < 8; r++) {
            float a = sub_s[(ig * 8 + r) * NPER + j];
            acc[r].x += a * sv.x;
            acc[r].y += a * sv.y;
            acc[r].z += a * sv.z;
            acc[r].w += a * sv.w;
        }
    }

    float4* zp = (float4*)(z + (size_t)b * NPER * DDIM);
#pragma unroll
    for (int r = 0; r < 8; r++)
        zp[(ig * 8 + r) * (DDIM / 4) + d4] = acc[r];
}

// ---------------------------------------------------------------------------
// kernel_launch
// ---------------------------------------------------------------------------
extern "C" void kernel_launch(void* const* d_in, const int* in_sizes, int n_in,
                              void* d_out, int out_size) {
    const float* A      = (const float*)d_in[0];
    const float* mu     = (const float*)d_in[1];
    const float* logstd = (const float*)d_in[2];
    const float* eps    = (const float*)d_in[3];
    const void*  nidx   = d_in[4];

    float* out_sigma = (float*)d_out;
    float* out_z     = out_sigma + SIGN;

    float* bufs = nullptr;
    cudaGetSymbolAddress((void**)&bufs, g_scratch);
    int* rows_dev = nullptr;
    cudaGetSymbolAddress((void**)&rows_dev, g_rows);

    float* BX   = bufs + 0 * M2;  // X, later P1=I+X, later Q3
    float* BX2  = bufs + 1 * M2;  // X^2, later Q2
    float* BX4  = bufs + 2 * M2;  // X^4, later P4
    float* BX8  = bufs + 3 * M2;  // X^8
    float* BX16 = bufs + 4 * M2;  // X^16
    float* BQ1  = bufs + 5 * M2;  // Q1, later S

    dim3 gT(MSZ / 32, MSZ / 32), bT(32, 8);
    dim3 gG(MSZ / BN, MSZ / BM);   // (16, 8) = 128 CTAs

    // Index dtype detect + convert (runs concurrently-safe, stream ordered)
    idx_detect_kernel<<<1, 256>>>((const unsigned int*)nidx);
    idx_convert_kernel<<<NIDX / 256, 256>>>(nidx);

    transpose_kernel<<<gT, bT>>>(A, BX);                  // X = A^T
    gemm_kernel<<<gG, 256>>>(BX, BX, nullptr, BX2);       // X2 = X*X
    diag_add_kernel<<<1, MSZ>>>(BX);                      // P1 = I+X
    gemm_kernel<<<gG, 256>>>(BX2, BX2, nullptr, BX4);     // X4
    gemm_kernel<<<gG, 256>>>(BX, BX2, BX, BQ1);           // Q1 = (I+X)(I+X2)
    gemm_kernel<<<gG, 256>>>(BX4, BX4, nullptr, BX8);     // X8
    diag_add_kernel<<<1, MSZ>>>(BX4);                     // P4 = I+X4
    gemm_kernel<<<gG, 256>>>(BX8, BX8, nullptr, BX16);    // X16
    gemm_kernel<<<gG, 256>>>(BX4, BX8, BX4, BX2);         // Q2 = (I+X4)(I+X8)
    gemm_kernel<<<gG, 256>>>(BQ1, BX2, nullptr, BX);      // Q3 = Q1*Q2
    gemm_kernel<<<gG, 256>>>(BX, BX16, BX, BQ1);          // S = Q3*(I+X16)

    sigma_kernel<<<SIGN / 4 / 256, 256>>>((const float4*)mu, (const float4*)logstd,
                                          (const float4*)eps, (float4*)out_sigma);

    cudaFuncSetAttribute(z_kernel, cudaFuncAttributeMaxDynamicSharedMemorySize, ZSMEM);
    z_kernel<<<NBAT, 256, ZSMEM>>>(BQ1, out_sigma, rows_dev, out_z);
}

// round 6
// speedup vs baseline: 1.3405x; 1.3405x over previous
#include <cuda_runtime.h>
#include <cuda_bf16.h>
#include <cuda_fp16.h>
#include <math.h>
#include <stdint.h>

#define MSZ   1024
#define M2    (MSZ * MSZ)
#define NPER  128
#define DDIM  64
#define NBAT  2048
#define NIDX  (NBAT * NPER)          // 262144
#define SIGN  (NBAT * NPER * DDIM)   // 16777216

// f32 scratch (6 x 4MB) + f16 split quads (6 matrices x {hi,lo,hiT,loT})
__device__ float g_scratch[6 * M2];
__device__ __half g_hf[6 * 4 * M2];
__device__ int g_rows[NIDX];
__device__ unsigned int g_odd_or;

__device__ __forceinline__ uint32_t smem_u32(const void* p) {
    uint32_t a;
    asm("{ .reg .u64 t; cvta.to.shared.u64 t, %1; cvt.u32.u64 %0, t; }" : "=r"(a) : "l"(p));
    return a;
}

// ---------------------------------------------------------------------------
// Index dtype detection + conversion (int64 vs int32 harness layout)
// ---------------------------------------------------------------------------
__global__ void idx_detect_kernel(const unsigned int* __restrict__ v32) {
    __shared__ unsigned int s[256];
    unsigned int o = 0;
    for (int i = threadIdx.x; i < NIDX / 2; i += 256) o |= v32[2 * i + 1];
    s[threadIdx.x] = o;
    __syncthreads();
    for (int d = 128; d > 0; d >>= 1) {
        if (threadIdx.x < d) s[threadIdx.x] |= s[threadIdx.x + d];
        __syncthreads();
    }
    if (threadIdx.x == 0) g_odd_or = s[0];
}
__global__ void idx_convert_kernel(const void* __restrict__ raw) {
    int i = blockIdx.x * blockDim.x + threadIdx.x;
    if (i >= NIDX) return;
    g_rows[i] = (g_odd_or == 0u) ? (int)((const long long*)raw)[i]
                                 : ((const int*)raw)[i];
}

// ---------------------------------------------------------------------------
// Transpose: T = A^T (f32)
// ---------------------------------------------------------------------------
__global__ void transpose_kernel(const float* __restrict__ A, float* __restrict__ T) {
    __shared__ float tile[32][33];
    int x = blockIdx.x * 32 + threadIdx.x;
    int y = blockIdx.y * 32 + threadIdx.y;
#pragma unroll
    for (int j = 0; j < 32; j += 8)
        tile[threadIdx.y + j][threadIdx.x] = A[(y + j) * MSZ + x];
    __syncthreads();
    x = blockIdx.y * 32 + threadIdx.x;
    y = blockIdx.x * 32 + threadIdx.y;
#pragma unroll
    for (int j = 0; j < 32; j += 8)
        T[(y + j) * MSZ + x] = tile[threadIdx.x][threadIdx.y + j];
}

__global__ void diag_add_kernel(float* M) {
    int i = blockIdx.x * blockDim.x + threadIdx.x;
    if (i < MSZ) M[i * MSZ + i] += 1.0f;
}

// ---------------------------------------------------------------------------
// Split f32 matrix R into f16 hi/lo + transposed hiT/loT
// ---------------------------------------------------------------------------
__global__ void cvt_kernel(const float* __restrict__ R,
                           __half* __restrict__ hi, __half* __restrict__ lo,
                           __half* __restrict__ hiT, __half* __restrict__ loT) {
    __shared__ float tile[32][33];
    int x = blockIdx.x * 32 + threadIdx.x;
    int y0 = blockIdx.y * 32 + threadIdx.y;
#pragma unroll
    for (int j = 0; j < 32; j += 8) {
        int y = y0 + j;
        float v = R[(size_t)y * MSZ + x];
        tile[threadIdx.y + j][threadIdx.x] = v;
        __half h = __float2half_rn(v);
        hi[(size_t)y * MSZ + x] = h;
        lo[(size_t)y * MSZ + x] = __float2half_rn(v - __half2float(h));
    }
    __syncthreads();
    int xT = blockIdx.y * 32 + threadIdx.x;
    int yT0 = blockIdx.x * 32 + threadIdx.y;
#pragma unroll
    for (int j = 0; j < 32; j += 8) {
        int yT = yT0 + j;
        float v = tile[threadIdx.x][threadIdx.y + j];
        __half h = __float2half_rn(v);
        hiT[(size_t)yT * MSZ + xT] = h;
        loT[(size_t)yT * MSZ + xT] = __float2half_rn(v - __half2float(h));
    }
}

// ---------------------------------------------------------------------------
// Tensor-core split-f16 GEMM via mma.sync (sm_80+ baseline PTX):
//   D = Ahi*Bhi + Alo*Bhi + Ahi*Blo (+C), all 1024x1024 f32 logical.
// CTA tile 128x64, BK=64 halves, 8 warps (4m x 2n), warp tile 32x32.
// B supplied transposed (BT row-major [n][k]) == col-major B for row.col mma.
// SMEM rows padded to 144B -> conflict-free ldmatrix + STS.128.
// ---------------------------------------------------------------------------
#define ROWB 144
#define ASTG (128 * ROWB)            // 18432
#define BSTG (64 * ROWB)             // 9216
#define STG  (ASTG + BSTG)           // 27648
#define GSMT (2 * STG)               // 55296

__device__ __forceinline__ void ldmx4(uint32_t* r, uint32_t addr) {
    asm volatile("ldmatrix.sync.aligned.m8n8.x4.shared.b16 {%0,%1,%2,%3}, [%4];"
                 : "=r"(r[0]), "=r"(r[1]), "=r"(r[2]), "=r"(r[3]) : "r"(addr));
}
__device__ __forceinline__ void mma16816(float* c, const uint32_t* a,
                                         uint32_t b0, uint32_t b1) {
    asm volatile(
        "mma.sync.aligned.m16n8k16.row.col.f32.f16.f16.f32 "
        "{%0,%1,%2,%3}, {%4,%5,%6,%7}, {%8,%9}, {%0,%1,%2,%3};"
        : "+f"(c[0]), "+f"(c[1]), "+f"(c[2]), "+f"(c[3])
        : "r"(a[0]), "r"(a[1]), "r"(a[2]), "r"(a[3]), "r"(b0), "r"(b1));
}

__global__ void __launch_bounds__(256) gemm_h_kernel(
    const __half* __restrict__ Ahi, const __half* __restrict__ Alo,
    const __half* __restrict__ BThi, const __half* __restrict__ BTlo,
    const float* __restrict__ Cm, float* __restrict__ Dm) {
    extern __shared__ char smem[];
    const int t = threadIdx.x;
    const int wid = t >> 5, lid = t & 31;
    const int m0 = blockIdx.y * 128, n0 = blockIdx.x * 64;
    const int wm = wid >> 1, wn = wid & 1;

    const __half* segA[3] = { Ahi, Alo, Ahi };
    const __half* segB[3] = { BThi, BThi, BTlo };

    // global->smem mapping
    const int ar = t >> 3, aq = t & 7;        // +256*i rows for A (4 iters)
    // ldmatrix lane addressing offsets
    const int lrow = (lid & 7) + ((lid >> 3) & 1) * 8;
    const int lkof = (lid >> 4) * 8;

    float acc[2][4][4];
#pragma unroll
    for (int i = 0; i < 2; i++)
#pragma unroll
        for (int j = 0; j < 4; j++)
#pragma unroll
            for (int e = 0; e < 4; e++) acc[i][j][e] = 0.0f;

    const uint32_t sbase = smem_u32(smem);

    // preload chunk 0
    {
        const __half* Ap = segA[0];
        const __half* Bp = segB[0];
        char* as = smem;
        char* bs = smem + ASTG;
#pragma unroll
        for (int i = 0; i < 4; i++) {
            int u = t + 256 * i, r = u >> 3, q = u & 7;
            *(uint4*)(as + r * ROWB + q * 16) =
                *(const uint4*)(Ap + (size_t)(m0 + r) * MSZ + q * 8);
        }
#pragma unroll
        for (int i = 0; i < 2; i++) {
            int u = t + 256 * i, r = u >> 3, q = u & 7;
            *(uint4*)(bs + r * ROWB + q * 16) =
                *(const uint4*)(Bp + (size_t)(n0 + r) * MSZ + q * 8);
        }
    }
    __syncthreads();

    for (int c = 0; c < 48; c++) {
        // prefetch chunk c+1 into registers
        uint4 apre[4], bpre[2];
        if (c < 47) {
            int cn = c + 1;
            const __half* Ap = segA[cn >> 4];
            const __half* Bp = segB[cn >> 4];
            int k0 = (cn & 15) * 64;
#pragma unroll
            for (int i = 0; i < 4; i++) {
                int u = t + 256 * i, r = u >> 3, q = u & 7;
                apre[i] = *(const uint4*)(Ap + (size_t)(m0 + r) * MSZ + k0 + q * 8);
            }
#pragma unroll
            for (int i = 0; i < 2; i++) {
                int u = t + 256 * i, r = u >> 3, q = u & 7;
                bpre[i] = *(const uint4*)(Bp + (size_t)(n0 + r) * MSZ + k0 + q * 8);
            }
        }

        // compute chunk c from smem stage (c&1)
        const uint32_t sa = sbase + (c & 1) * STG;
        const uint32_t sb = sa + ASTG;
#pragma unroll
        for (int ks = 0; ks < 4; ks++) {
            uint32_t af[2][4], bf[2][4];
#pragma unroll
            for (int i = 0; i < 2; i++)
                ldmx4(af[i], sa + (uint32_t)((wm * 32 + i * 16 + lrow) * ROWB +
                                             (ks * 16 + lkof) * 2));
#pragma unroll
            for (int j2 = 0; j2 < 2; j2++)
                ldmx4(bf[j2], sb + (uint32_t)((wn * 32 + j2 * 16 + lrow) * ROWB +
                                              (ks * 16 + lkof) * 2));
#pragma unroll
            for (int i = 0; i < 2; i++)
#pragma unroll
                for (int j = 0; j < 4; j++)
                    mma16816(acc[i][j], af[i], bf[j >> 1][j & 1], bf[j >> 1][(j & 1) + 2]);
        }
        __syncthreads();

        if (c < 47) {
            char* as = smem + ((c + 1) & 1) * STG;
            char* bs = as + ASTG;
#pragma unroll
            for (int i = 0; i < 4; i++) {
                int u = t + 256 * i, r = u >> 3, q = u & 7;
                *(uint4*)(as + r * ROWB + q * 16) = apre[i];
            }
#pragma unroll
            for (int i = 0; i < 2; i++) {
                int u = t + 256 * i, r = u >> 3, q = u & 7;
                *(uint4*)(bs + r * ROWB + q * 16) = bpre[i];
            }
        }
        __syncthreads();
    }

    // Epilogue: c-frag layout -> coalesced float2 stores
    const int g = lid >> 2, q = lid & 3;
#pragma unroll
    for (int i = 0; i < 2; i++) {
#pragma unroll
        for (int j = 0; j < 4; j++) {
            int r0 = m0 + wm * 32 + i * 16 + g;
            int r1 = r0 + 8;
            int cc = n0 + wn * 32 + j * 8 + q * 2;
            float2 v0 = make_float2(acc[i][j][0], acc[i][j][1]);
            float2 v1 = make_float2(acc[i][j][2], acc[i][j][3]);
            if (Cm) {
                float2 c0 = *(const float2*)&Cm[(size_t)r0 * MSZ + cc];
                float2 c1 = *(const float2*)&Cm[(size_t)r1 * MSZ + cc];
                v0.x += c0.x; v0.y += c0.y;
                v1.x += c1.x; v1.y += c1.y;
            }
            *(float2*)&Dm[(size_t)r0 * MSZ + cc] = v0;
            *(float2*)&Dm[(size_t)r1 * MSZ + cc] = v1;
        }
    }
}

// ---------------------------------------------------------------------------
// sigma = mu + eps * exp(logstd)
// ---------------------------------------------------------------------------
__global__ void sigma_kernel(const float4* __restrict__ mu,
                             const float4* __restrict__ ls,
                             const float4* __restrict__ ep,
                             float4* __restrict__ out) {
    int i = blockIdx.x * blockDim.x + threadIdx.x;
    float4 m = mu[i], l = ls[i], e = ep[i];
    float4 r;
    r.x = m.x + e.x * expf(l.x);
    r.y = m.y + e.y * expf(l.y);
    r.z = m.z + e.z * expf(l.z);
    r.w = m.w + e.w * expf(l.w);
    out[i] = r;
}

// ---------------------------------------------------------------------------
// z[b] = S[idx[b],:][:,idx[b]] @ sigma[b]  (one CTA per batch)
// ---------------------------------------------------------------------------
#define ZSMEM ((NPER * NPER + NPER * DDIM + NPER) * 4)
__global__ void __launch_bounds__(256) z_kernel(
    const float* __restrict__ S, const float* __restrict__ sigma,
    const int* __restrict__ ridx, float* __restrict__ z) {
    extern __shared__ float zsm[];
    float* sub_s = zsm;
    float* sig_s = zsm + NPER * NPER;
    int*   rows  = (int*)(sig_s + NPER * DDIM);

    const int b = blockIdx.x;
    const int t = threadIdx.x;

    if (t < NPER) rows[t] = ridx[b * NPER + t];
    {
        const float4* sg = (const float4*)(sigma + (size_t)b * NPER * DDIM);
        float4* ss = (float4*)sig_s;
        for (int i = t; i < NPER * DDIM / 4; i += 256) ss[i] = sg[i];
    }
    __syncthreads();
    {
        const int tj  = t & 127;
        const int ti0 = (t >> 7) * 64;
        const int cj  = rows[tj];
#pragma unroll 4
        for (int ii = 0; ii < 64; ii++) {
            int i = ti0 + ii;
            sub_s[i * NPER + tj] = S[(size_t)rows[i] * MSZ + cj];
        }
    }
    __syncthreads();

    const int d4 = t & 15;
    const int ig = t >> 4;
    float4 acc[8];
#pragma unroll
    for (int r = 0; r < 8; r++) acc[r] = make_float4(0.f, 0.f, 0.f, 0.f);

    const float4* sig4 = (const float4*)sig_s;
    for (int j = 0; j < NPER; j++) {
        float4 sv = sig4[j * (DDIM / 4) + d4];
#pragma unroll
        for (int r = 0; r < 8; r++) {
            float a = sub_s[(ig * 8 + r) * NPER + j];
            acc[r].x += a * sv.x;
            acc[r].y += a * sv.y;
            acc[r].z += a * sv.z;
            acc[r].w += a * sv.w;
        }
    }
    float4* zp = (float4*)(z + (size_t)b * NPER * DDIM);
#pragma unroll
    for (int r = 0; r < 8; r++)
        zp[(ig * 8 + r) * (DDIM / 4) + d4] = acc[r];
}

// ---------------------------------------------------------------------------
// kernel_launch
// ---------------------------------------------------------------------------
extern "C" void kernel_launch(void* const* d_in, const int* in_sizes, int n_in,
                              void* d_out, int out_size) {
    const float* A      = (const float*)d_in[0];
    const float* mu     = (const float*)d_in[1];
    const float* logstd = (const float*)d_in[2];
    const float* eps    = (const float*)d_in[3];
    const void*  nidx   = d_in[4];

    float* out_sigma = (float*)d_out;
    float* out_z     = out_sigma + SIGN;

    float* bufs = nullptr;
    cudaGetSymbolAddress((void**)&bufs, g_scratch);
    __half* hfb = nullptr;
    cudaGetSymbolAddress((void**)&hfb, g_hf);
    int* rows_dev = nullptr;
    cudaGetSymbolAddress((void**)&rows_dev, g_rows);

    float* BX   = bufs + 0 * M2;  // X -> P1 -> Q3
    float* BX2  = bufs + 1 * M2;  // X2 -> Q2
    float* BX4  = bufs + 2 * M2;  // X4 -> P4
    float* BX8  = bufs + 3 * M2;
    float* BX16 = bufs + 4 * M2;
    float* BQ1  = bufs + 5 * M2;  // Q1 -> S

    auto Q = [&](int q, int p) { return hfb + ((size_t)(q * 4 + p)) * M2; };

    dim3 gT(MSZ / 32, MSZ / 32), bT(32, 8);
    dim3 gG(MSZ / 64, MSZ / 128);   // (16, 8) = 128 CTAs

    cudaFuncSetAttribute(gemm_h_kernel, cudaFuncAttributeMaxDynamicSharedMemorySize, GSMT);
    cudaFuncSetAttribute(z_kernel, cudaFuncAttributeMaxDynamicSharedMemorySize, ZSMEM);

    idx_detect_kernel<<<1, 256>>>((const unsigned int*)nidx);
    idx_convert_kernel<<<NIDX / 256, 256>>>(nidx);

#define GEMM_T(qa, qb, Cp, Dp) \
    gemm_h_kernel<<<gG, 256, GSMT>>>(Q(qa,0), Q(qa,1), Q(qb,2), Q(qb,3), Cp, Dp)

    transpose_kernel<<<gT, bT>>>(A, BX);                         // X = A^T
    cvt_kernel<<<gT, bT>>>(BX, Q(0,0), Q(0,1), Q(0,2), Q(0,3));  // q0 = X
    GEMM_T(0, 0, (const float*)nullptr, BX2);                    // X2 = X*X
    diag_add_kernel<<<1, MSZ>>>(BX);                             // P1 = I+X
    cvt_kernel<<<gT, bT>>>(BX, Q(0,0), Q(0,1), Q(0,2), Q(0,3));  // q0 = P1
    cvt_kernel<<<gT, bT>>>(BX2, Q(1,0), Q(1,1), Q(1,2), Q(1,3)); // q1 = X2
    GEMM_T(1, 1, (const float*)nullptr, BX4);                    // X4 = X2*X2
    GEMM_T(0, 1, BX, BQ1);                                       // Q1 = P1*X2 + P1
    cvt_kernel<<<gT, bT>>>(BX4, Q(2,0), Q(2,1), Q(2,2), Q(2,3)); // q2 = X4
    GEMM_T(2, 2, (const float*)nullptr, BX8);                    // X8 = X4*X4
    diag_add_kernel<<<1, MSZ>>>(BX4);                            // P4 = I+X4
    cvt_kernel<<<gT, bT>>>(BX4, Q(2,0), Q(2,1), Q(2,2), Q(2,3)); // q2 = P4
    cvt_kernel<<<gT, bT>>>(BX8, Q(3,0), Q(3,1), Q(3,2), Q(3,3)); // q3 = X8
    GEMM_T(3, 3, (const float*)nullptr, BX16);                   // X16 = X8*X8
    GEMM_T(2, 3, BX4, BX2);                                      // Q2 = P4*X8 + P4
    cvt_kernel<<<gT, bT>>>(BX16, Q(4,0), Q(4,1), Q(4,2), Q(4,3));// q4 = X16
    cvt_kernel<<<gT, bT>>>(BQ1, Q(5,0), Q(5,1), Q(5,2), Q(5,3)); // q5 = Q1
    cvt_kernel<<<gT, bT>>>(BX2, Q(1,0), Q(1,1), Q(1,2), Q(1,3)); // q1 = Q2
    GEMM_T(5, 1, (const float*)nullptr, BX);                     // Q3 = Q1*Q2
    cvt_kernel<<<gT, bT>>>(BX, Q(2,0), Q(2,1), Q(2,2), Q(2,3));  // q2 = Q3
    GEMM_T(2, 4, BX, BQ1);                                       // S = Q3*X16 + Q3

    sigma_kernel<<<SIGN / 4 / 256, 256>>>((const float4*)mu, (const float4*)logstd,
                                          (const float4*)eps, (float4*)out_sigma);

    z_kernel<<<NBAT, 256, ZSMEM>>>(BQ1, out_sigma, rows_dev, out_z);
#undef GEMM_T
}

// round 7
// speedup vs baseline: 1.9858x; 1.4814x over previous
#include <cuda_runtime.h>
#include <cuda_bf16.h>
#include <cuda_fp16.h>
#include <math.h>
#include <stdint.h>

#define MSZ   1024
#define M2    (MSZ * MSZ)
#define NPER  128
#define DDIM  64
#define NBAT  2048
#define NIDX  (NBAT * NPER)          // 262144
#define SIGN  (NBAT * NPER * DDIM)   // 16777216

// f32 scratch (6 x 4MB) + f16 split quads (6 matrices x {hi,lo,hiT,loT})
__device__ float g_scratch[6 * M2];
__device__ __half g_hf[6 * 4 * M2];
__device__ int g_rows[NIDX];
__device__ unsigned int g_odd_or;

__device__ __forceinline__ uint32_t smem_u32(const void* p) {
    uint32_t a;
    asm("{ .reg .u64 t; cvta.to.shared.u64 t, %1; cvt.u32.u64 %0, t; }" : "=r"(a) : "l"(p));
    return a;
}
// f32x2 packed helpers
__device__ __forceinline__ unsigned long long pack2(float x, float y) {
    unsigned long long r;
    asm("mov.b64 %0, {%1, %2};" : "=l"(r) : "f"(x), "f"(y));
    return r;
}
__device__ __forceinline__ void fma2(unsigned long long& d,
                                     unsigned long long a, unsigned long long b) {
    asm("fma.rn.f32x2 %0, %1, %2, %0;" : "+l"(d) : "l"(a), "l"(b));
}
__device__ __forceinline__ void unpack2(unsigned long long v, float& lo, float& hi) {
    asm("mov.b64 {%0, %1}, %2;" : "=f"(lo), "=f"(hi) : "l"(v));
}

// ---------------------------------------------------------------------------
// Index dtype detection + conversion (int64 vs int32 harness layout)
// ---------------------------------------------------------------------------
__global__ void idx_detect_kernel(const unsigned int* __restrict__ v32) {
    __shared__ unsigned int s[256];
    unsigned int o = 0;
    for (int i = threadIdx.x; i < NIDX / 2; i += 256) o |= v32[2 * i + 1];
    s[threadIdx.x] = o;
    __syncthreads();
    for (int d = 128; d > 0; d >>= 1) {
        if (threadIdx.x < d) s[threadIdx.x] |= s[threadIdx.x + d];
        __syncthreads();
    }
    if (threadIdx.x == 0) g_odd_or = s[0];
}
__global__ void idx_convert_kernel(const void* __restrict__ raw) {
    int i = blockIdx.x * blockDim.x + threadIdx.x;
    if (i >= NIDX) return;
    g_rows[i] = (g_odd_or == 0u) ? (int)((const long long*)raw)[i]
                                 : ((const int*)raw)[i];
}

// ---------------------------------------------------------------------------
// Transpose: T = A^T (f32)
// ---------------------------------------------------------------------------
__global__ void transpose_kernel(const float* __restrict__ A, float* __restrict__ T) {
    __shared__ float tile[32][33];
    int x = blockIdx.x * 32 + threadIdx.x;
    int y = blockIdx.y * 32 + threadIdx.y;
#pragma unroll
    for (int j = 0; j < 32; j += 8)
        tile[threadIdx.y + j][threadIdx.x] = A[(y + j) * MSZ + x];
    __syncthreads();
    x = blockIdx.y * 32 + threadIdx.x;
    y = blockIdx.x * 32 + threadIdx.y;
#pragma unroll
    for (int j = 0; j < 32; j += 8)
        T[(y + j) * MSZ + x] = tile[threadIdx.x][threadIdx.y + j];
}

__global__ void diag_add_kernel(float* M) {
    int i = blockIdx.x * blockDim.x + threadIdx.x;
    if (i < MSZ) M[i * MSZ + i] += 1.0f;
}

// ---------------------------------------------------------------------------
// Split f32 matrix R into f16 hi/lo + transposed hiT/loT
// ---------------------------------------------------------------------------
__global__ void cvt_kernel(const float* __restrict__ R,
                           __half* __restrict__ hi, __half* __restrict__ lo,
                           __half* __restrict__ hiT, __half* __restrict__ loT) {
    __shared__ float tile[32][33];
    int x = blockIdx.x * 32 + threadIdx.x;
    int y0 = blockIdx.y * 32 + threadIdx.y;
#pragma unroll
    for (int j = 0; j < 32; j += 8) {
        int y = y0 + j;
        float v = R[(size_t)y * MSZ + x];
        tile[threadIdx.y + j][threadIdx.x] = v;
        __half h = __float2half_rn(v);
        hi[(size_t)y * MSZ + x] = h;
        lo[(size_t)y * MSZ + x] = __float2half_rn(v - __half2float(h));
    }
    __syncthreads();
    int xT = blockIdx.y * 32 + threadIdx.x;
    int yT0 = blockIdx.x * 32 + threadIdx.y;
#pragma unroll
    for (int j = 0; j < 32; j += 8) {
        int yT = yT0 + j;
        float v = tile[threadIdx.x][threadIdx.y + j];
        __half h = __float2half_rn(v);
        hiT[(size_t)yT * MSZ + xT] = h;
        loT[(size_t)yT * MSZ + xT] = __float2half_rn(v - __half2float(h));
    }
}

// ---------------------------------------------------------------------------
// Tensor-core f16 GEMM via mma.sync, precision-tiered:
//   nseg=1: D = Ahi*Bhi (+C)                     (plain f16)
//   nseg=3: D = Ahi*Bhi + Alo*Bhi + Ahi*Blo (+C) (split f16)
// CTA tile 128x64, BK=64, 8 warps (4m x 2n), warp tile 32x32, double-buffered.
// ---------------------------------------------------------------------------
#define ROWB 144
#define ASTG (128 * ROWB)
#define BSTG (64 * ROWB)
#define STG  (ASTG + BSTG)
#define GSMT (2 * STG)

__device__ __forceinline__ void ldmx4(uint32_t* r, uint32_t addr) {
    asm volatile("ldmatrix.sync.aligned.m8n8.x4.shared.b16 {%0,%1,%2,%3}, [%4];"
                 : "=r"(r[0]), "=r"(r[1]), "=r"(r[2]), "=r"(r[3]) : "r"(addr));
}
__device__ __forceinline__ void mma16816(float* c, const uint32_t* a,
                                         uint32_t b0, uint32_t b1) {
    asm volatile(
        "mma.sync.aligned.m16n8k16.row.col.f32.f16.f16.f32 "
        "{%0,%1,%2,%3}, {%4,%5,%6,%7}, {%8,%9}, {%0,%1,%2,%3};"
        : "+f"(c[0]), "+f"(c[1]), "+f"(c[2]), "+f"(c[3])
        : "r"(a[0]), "r"(a[1]), "r"(a[2]), "r"(a[3]), "r"(b0), "r"(b1));
}

__global__ void __launch_bounds__(256) gemm_h_kernel(
    const __half* __restrict__ Ahi, const __half* __restrict__ Alo,
    const __half* __restrict__ BThi, const __half* __restrict__ BTlo,
    const float* __restrict__ Cm, float* __restrict__ Dm, int nseg) {
    extern __shared__ char smem[];
    const int t = threadIdx.x;
    const int wid = t >> 5, lid = t & 31;
    const int m0 = blockIdx.y * 128, n0 = blockIdx.x * 64;
    const int wm = wid >> 1, wn = wid & 1;
    const int CMAX = nseg << 4;

    const __half* segA[3] = { Ahi, Alo, Ahi };
    const __half* segB[3] = { BThi, BThi, BTlo };

    const int lrow = (lid & 7) + ((lid >> 3) & 1) * 8;
    const int lkof = (lid >> 4) * 8;

    float acc[2][4][4];
#pragma unroll
    for (int i = 0; i < 2; i++)
#pragma unroll
        for (int j = 0; j < 4; j++)
#pragma unroll
            for (int e = 0; e < 4; e++) acc[i][j][e] = 0.0f;

    const uint32_t sbase = smem_u32(smem);

    // preload chunk 0
    {
        const __half* Ap = segA[0];
        const __half* Bp = segB[0];
        char* as = smem;
        char* bs = smem + ASTG;
#pragma unroll
        for (int i = 0; i < 4; i++) {
            int u = t + 256 * i, r = u >> 3, q = u & 7;
            *(uint4*)(as + r * ROWB + q * 16) =
                *(const uint4*)(Ap + (size_t)(m0 + r) * MSZ + q * 8);
        }
#pragma unroll
        for (int i = 0; i < 2; i++) {
            int u = t + 256 * i, r = u >> 3, q = u & 7;
            *(uint4*)(bs + r * ROWB + q * 16) =
                *(const uint4*)(Bp + (size_t)(n0 + r) * MSZ + q * 8);
        }
    }
    __syncthreads();

    for (int c = 0; c < CMAX; c++) {
        uint4 apre[4], bpre[2];
        if (c < CMAX - 1) {
            int cn = c + 1;
            const __half* Ap = segA[cn >> 4];
            const __half* Bp = segB[cn >> 4];
            int k0 = (cn & 15) * 64;
#pragma unroll
            for (int i = 0; i < 4; i++) {
                int u = t + 256 * i, r = u >> 3, q = u & 7;
                apre[i] = *(const uint4*)(Ap + (size_t)(m0 + r) * MSZ + k0 + q * 8);
            }
#pragma unroll
            for (int i = 0; i < 2; i++) {
                int u = t + 256 * i, r = u >> 3, q = u & 7;
                bpre[i] = *(const uint4*)(Bp + (size_t)(n0 + r) * MSZ + k0 + q * 8);
            }
        }

        const uint32_t sa = sbase + (c & 1) * STG;
        const uint32_t sb = sa + ASTG;
#pragma unroll
        for (int ks = 0; ks < 4; ks++) {
            uint32_t af[2][4], bf[2][4];
#pragma unroll
            for (int i = 0; i < 2; i++)
                ldmx4(af[i], sa + (uint32_t)((wm * 32 + i * 16 + lrow) * ROWB +
                                             (ks * 16 + lkof) * 2));
#pragma unroll
            for (int j2 = 0; j2 < 2; j2++)
                ldmx4(bf[j2], sb + (uint32_t)((wn * 32 + j2 * 16 + lrow) * ROWB +
                                              (ks * 16 + lkof) * 2));
#pragma unroll
            for (int i = 0; i < 2; i++)
#pragma unroll
                for (int j = 0; j < 4; j++)
                    mma16816(acc[i][j], af[i], bf[j >> 1][j & 1], bf[j >> 1][(j & 1) + 2]);
        }
        __syncthreads();

        if (c < CMAX - 1) {
            char* as = smem + ((c + 1) & 1) * STG;
            char* bs = as + ASTG;
#pragma unroll
            for (int i = 0; i < 4; i++) {
                int u = t + 256 * i, r = u >> 3, q = u & 7;
                *(uint4*)(as + r * ROWB + q * 16) = apre[i];
            }
#pragma unroll
            for (int i = 0; i < 2; i++) {
                int u = t + 256 * i, r = u >> 3, q = u & 7;
                *(uint4*)(bs + r * ROWB + q * 16) = bpre[i];
            }
        }
        __syncthreads();
    }

    const int g = lid >> 2, q = lid & 3;
#pragma unroll
    for (int i = 0; i < 2; i++) {
#pragma unroll
        for (int j = 0; j < 4; j++) {
            int r0 = m0 + wm * 32 + i * 16 + g;
            int r1 = r0 + 8;
            int cc = n0 + wn * 32 + j * 8 + q * 2;
            float2 v0 = make_float2(acc[i][j][0], acc[i][j][1]);
            float2 v1 = make_float2(acc[i][j][2], acc[i][j][3]);
            if (Cm) {
                float2 c0 = *(const float2*)&Cm[(size_t)r0 * MSZ + cc];
                float2 c1 = *(const float2*)&Cm[(size_t)r1 * MSZ + cc];
                v0.x += c0.x; v0.y += c0.y;
                v1.x += c1.x; v1.y += c1.y;
            }
            *(float2*)&Dm[(size_t)r0 * MSZ + cc] = v0;
            *(float2*)&Dm[(size_t)r1 * MSZ + cc] = v1;
        }
    }
}

// ---------------------------------------------------------------------------
// sigma = mu + eps * exp(logstd)
// ---------------------------------------------------------------------------
__global__ void sigma_kernel(const float4* __restrict__ mu,
                             const float4* __restrict__ ls,
                             const float4* __restrict__ ep,
                             float4* __restrict__ out) {
    int i = blockIdx.x * blockDim.x + threadIdx.x;
    float4 m = mu[i], l = ls[i], e = ep[i];
    float4 r;
    r.x = m.x + e.x * expf(l.x);
    r.y = m.y + e.y * expf(l.y);
    r.z = m.z + e.z * expf(l.z);
    r.w = m.w + e.w * expf(l.w);
    out[i] = r;
}

// ---------------------------------------------------------------------------
// z[b] = S[idx[b],:][:,idx[b]] @ sigma[b]  (one CTA per batch), FFMA2 inner
// ---------------------------------------------------------------------------
#define ZSMEM ((NPER * NPER + NPER * DDIM + NPER) * 4)
__global__ void __launch_bounds__(256) z_kernel(
    const float* __restrict__ S, const float* __restrict__ sigma,
    const int* __restrict__ ridx, float* __restrict__ z) {
    extern __shared__ float zsm[];
    float* sub_s = zsm;
    float* sig_s = zsm + NPER * NPER;
    int*   rows  = (int*)(sig_s + NPER * DDIM);

    const int b = blockIdx.x;
    const int t = threadIdx.x;

    if (t < NPER) rows[t] = ridx[b * NPER + t];
    {
        const float4* sg = (const float4*)(sigma + (size_t)b * NPER * DDIM);
        float4* ss = (float4*)sig_s;
        for (int i = t; i < NPER * DDIM / 4; i += 256) ss[i] = sg[i];
    }
    __syncthreads();
    {
        const int tj  = t & 127;
        const int ti0 = (t >> 7) * 64;
        const int cj  = rows[tj];
#pragma unroll 4
        for (int ii = 0; ii < 64; ii++) {
            int i = ti0 + ii;
            sub_s[i * NPER + tj] = S[(size_t)rows[i] * MSZ + cj];
        }
    }
    __syncthreads();

    const int d4 = t & 15;
    const int ig = t >> 4;
    unsigned long long accA[8], accB[8];
#pragma unroll
    for (int r = 0; r < 8; r++) { accA[r] = 0ull; accB[r] = 0ull; }

    const float4* sig4 = (const float4*)sig_s;
    for (int j = 0; j < NPER; j++) {
        float4 sv = sig4[j * (DDIM / 4) + d4];
        unsigned long long sxy = pack2(sv.x, sv.y);
        unsigned long long szw = pack2(sv.z, sv.w);
#pragma unroll
        for (int r = 0; r < 8; r++) {
            float a = sub_s[(ig * 8 + r) * NPER + j];
            unsigned long long aa = pack2(a, a);
            fma2(accA[r], aa, sxy);
            fma2(accB[r], aa, szw);
        }
    }
    float4* zp = (float4*)(z + (size_t)b * NPER * DDIM);
#pragma unroll
    for (int r = 0; r < 8; r++) {
        float4 v;
        unpack2(accA[r], v.x, v.y);
        unpack2(accB[r], v.z, v.w);
        zp[(ig * 8 + r) * (DDIM / 4) + d4] = v;
    }
}

// ---------------------------------------------------------------------------
// kernel_launch
// ---------------------------------------------------------------------------
extern "C" void kernel_launch(void* const* d_in, const int* in_sizes, int n_in,
                              void* d_out, int out_size) {
    const float* A      = (const float*)d_in[0];
    const float* mu     = (const float*)d_in[1];
    const float* logstd = (const float*)d_in[2];
    const float* eps    = (const float*)d_in[3];
    const void*  nidx   = d_in[4];

    float* out_sigma = (float*)d_out;
    float* out_z     = out_sigma + SIGN;

    float* bufs = nullptr;
    cudaGetSymbolAddress((void**)&bufs, g_scratch);
    __half* hfb = nullptr;
    cudaGetSymbolAddress((void**)&hfb, g_hf);
    int* rows_dev = nullptr;
    cudaGetSymbolAddress((void**)&rows_dev, g_rows);

    float* BX   = bufs + 0 * M2;  // X -> P1 -> Q3
    float* BX2  = bufs + 1 * M2;  // X2 -> Q2
    float* BX4  = bufs + 2 * M2;  // X4 -> P4
    float* BX8  = bufs + 3 * M2;
    float* BX16 = bufs + 4 * M2;
    float* BQ1  = bufs + 5 * M2;  // Q1 -> S

    auto Q = [&](int q, int p) { return hfb + ((size_t)(q * 4 + p)) * M2; };

    dim3 gT(MSZ / 32, MSZ / 32), bT(32, 8);
    dim3 gG(MSZ / 64, MSZ / 128);   // (16, 8) = 128 CTAs

    cudaFuncSetAttribute(gemm_h_kernel, cudaFuncAttributeMaxDynamicSharedMemorySize, GSMT);
    cudaFuncSetAttribute(z_kernel, cudaFuncAttributeMaxDynamicSharedMemorySize, ZSMEM);

    idx_detect_kernel<<<1, 256>>>((const unsigned int*)nidx);
    idx_convert_kernel<<<NIDX / 256, 256>>>(nidx);

#define GEMM_T(qa, qb, Cp, Dp, ns) \
    gemm_h_kernel<<<gG, 256, GSMT>>>(Q(qa,0), Q(qa,1), Q(qb,2), Q(qb,3), Cp, Dp, ns)

    transpose_kernel<<<gT, bT>>>(A, BX);                         // X = A^T
    cvt_kernel<<<gT, bT>>>(BX, Q(0,0), Q(0,1), Q(0,2), Q(0,3));  // q0 = X
    GEMM_T(0, 0, (const float*)nullptr, BX2, 1);                 // X2 = X*X          (plain)
    diag_add_kernel<<<1, MSZ>>>(BX);                             // P1 = I+X
    cvt_kernel<<<gT, bT>>>(BX, Q(0,0), Q(0,1), Q(0,2), Q(0,3));  // q0 = P1
    cvt_kernel<<<gT, bT>>>(BX2, Q(1,0), Q(1,1), Q(1,2), Q(1,3)); // q1 = X2
    GEMM_T(1, 1, (const float*)nullptr, BX4, 1);                 // X4 = X2*X2        (plain)
    GEMM_T(0, 1, BX, BQ1, 1);                                    // Q1 = P1*X2 + P1   (plain)
    cvt_kernel<<<gT, bT>>>(BX4, Q(2,0), Q(2,1), Q(2,2), Q(2,3)); // q2 = X4
    GEMM_T(2, 2, (const float*)nullptr, BX8, 1);                 // X8 = X4*X4        (plain)
    diag_add_kernel<<<1, MSZ>>>(BX4);                            // P4 = I+X4
    cvt_kernel<<<gT, bT>>>(BX4, Q(2,0), Q(2,1), Q(2,2), Q(2,3)); // q2 = P4
    cvt_kernel<<<gT, bT>>>(BX8, Q(3,0), Q(3,1), Q(3,2), Q(3,3)); // q3 = X8
    GEMM_T(3, 3, (const float*)nullptr, BX16, 1);                // X16 = X8*X8       (plain)
    GEMM_T(2, 3, BX4, BX2, 1);                                   // Q2 = P4*X8 + P4   (plain)
    cvt_kernel<<<gT, bT>>>(BX16, Q(4,0), Q(4,1), Q(4,2), Q(4,3));// q4 = X16
    cvt_kernel<<<gT, bT>>>(BQ1, Q(5,0), Q(5,1), Q(5,2), Q(5,3)); // q5 = Q1
    cvt_kernel<<<gT, bT>>>(BX2, Q(1,0), Q(1,1), Q(1,2), Q(1,3)); // q1 = Q2
    GEMM_T(5, 1, (const float*)nullptr, BX, 3);                  // Q3 = Q1*Q2        (SPLIT)
    cvt_kernel<<<gT, bT>>>(BX, Q(2,0), Q(2,1), Q(2,2), Q(2,3));  // q2 = Q3
    GEMM_T(2, 4, BX, BQ1, 1);                                    // S = Q3*X16 + Q3   (plain)

    sigma_kernel<<<SIGN / 4 / 256, 256>>>((const float4*)mu, (const float4*)logstd,
                                          (const float4*)eps, (float4*)out_sigma);

    z_kernel<<<NBAT, 256, ZSMEM>>>(BQ1, out_sigma, rows_dev, out_z);
#undef GEMM_T
}

// round 8
// speedup vs baseline: 2.1979x; 1.1068x over previous
#include <cuda_runtime.h>
#include <cuda_bf16.h>
#include <cuda_fp16.h>
#include <math.h>
#include <stdint.h>

#define MSZ   1024
#define M2    (MSZ * MSZ)
#define NPER  128
#define DDIM  64
#define NBAT  2048
#define NIDX  (NBAT * NPER)          // 262144
#define SIGN  (NBAT * NPER * DDIM)   // 16777216

// f32 scratch (6 x 4MB) + f16 split quads (6 matrices x {hi,lo,hiT,loT})
__device__ float g_scratch[6 * M2];
__device__ __half g_hf[6 * 4 * M2];
__device__ int g_rows[NIDX];
__device__ unsigned int g_odd_or;

__device__ __forceinline__ uint32_t smem_u32(const void* p) {
    uint32_t a;
    asm("{ .reg .u64 t; cvta.to.shared.u64 t, %1; cvt.u32.u64 %0, t; }" : "=r"(a) : "l"(p));
    return a;
}
// f32x2 packed helpers
__device__ __forceinline__ unsigned long long pack2(float x, float y) {
    unsigned long long r;
    asm("mov.b64 %0, {%1, %2};" : "=l"(r) : "f"(x), "f"(y));
    return r;
}
__device__ __forceinline__ void fma2(unsigned long long& d,
                                     unsigned long long a, unsigned long long b) {
    asm("fma.rn.f32x2 %0, %1, %2, %0;" : "+l"(d) : "l"(a), "l"(b));
}
__device__ __forceinline__ void unpack2(unsigned long long v, float& lo, float& hi) {
    asm("mov.b64 {%0, %1}, %2;" : "=f"(lo), "=f"(hi) : "l"(v));
}

// ---------------------------------------------------------------------------
// Index dtype detection + conversion (int64 vs int32 harness layout)
// ---------------------------------------------------------------------------
__global__ void idx_detect_kernel(const unsigned int* __restrict__ v32) {
    __shared__ unsigned int s[256];
    unsigned int o = 0;
    for (int i = threadIdx.x; i < NIDX / 2; i += 256) o |= v32[2 * i + 1];
    s[threadIdx.x] = o;
    __syncthreads();
    for (int d = 128; d > 0; d >>= 1) {
        if (threadIdx.x < d) s[threadIdx.x] |= s[threadIdx.x + d];
        __syncthreads();
    }
    if (threadIdx.x == 0) g_odd_or = s[0];
}
__global__ void idx_convert_kernel(const void* __restrict__ raw) {
    int i = blockIdx.x * blockDim.x + threadIdx.x;
    if (i >= NIDX) return;
    g_rows[i] = (g_odd_or == 0u) ? (int)((const long long*)raw)[i]
                                 : ((const int*)raw)[i];
}

// ---------------------------------------------------------------------------
// Transpose: T = A^T (f32)
// ---------------------------------------------------------------------------
__global__ void transpose_kernel(const float* __restrict__ A, float* __restrict__ T) {
    __shared__ float tile[32][33];
    int x = blockIdx.x * 32 + threadIdx.x;
    int y = blockIdx.y * 32 + threadIdx.y;
#pragma unroll
    for (int j = 0; j < 32; j += 8)
        tile[threadIdx.y + j][threadIdx.x] = A[(y + j) * MSZ + x];
    __syncthreads();
    x = blockIdx.y * 32 + threadIdx.x;
    y = blockIdx.x * 32 + threadIdx.y;
#pragma unroll
    for (int j = 0; j < 32; j += 8)
        T[(y + j) * MSZ + x] = tile[threadIdx.x][threadIdx.y + j];
}

// ---------------------------------------------------------------------------
// Split f32 matrix (optionally +I) into f16 hi/lo + transposed hiT/loT
// ---------------------------------------------------------------------------
__global__ void cvt_kernel(const float* __restrict__ R,
                           __half* __restrict__ hi, __half* __restrict__ lo,
                           __half* __restrict__ hiT, __half* __restrict__ loT,
                           int addI) {
    __shared__ float tile[32][33];
    int x = blockIdx.x * 32 + threadIdx.x;
    int y0 = blockIdx.y * 32 + threadIdx.y;
#pragma unroll
    for (int j = 0; j < 32; j += 8) {
        int y = y0 + j;
        float v = R[(size_t)y * MSZ + x];
        if (addI && y == x) v += 1.0f;
        tile[threadIdx.y + j][threadIdx.x] = v;
        __half h = __float2half_rn(v);
        hi[(size_t)y * MSZ + x] = h;
        lo[(size_t)y * MSZ + x] = __float2half_rn(v - __half2float(h));
    }
    __syncthreads();
    int xT = blockIdx.y * 32 + threadIdx.x;
    int yT0 = blockIdx.x * 32 + threadIdx.y;
#pragma unroll
    for (int j = 0; j < 32; j += 8) {
        int yT = yT0 + j;
        float v = tile[threadIdx.x][threadIdx.y + j];
        __half h = __float2half_rn(v);
        hiT[(size_t)yT * MSZ + xT] = h;
        loT[(size_t)yT * MSZ + xT] = __float2half_rn(v - __half2float(h));
    }
}

// ---------------------------------------------------------------------------
// Tensor-core f16 GEMM via mma.sync, precision-tiered:
//   nseg=1: D = Ahi*Bhi (+C) (+I)
//   nseg=3: D = Ahi*Bhi + Alo*Bhi + Ahi*Blo (+C) (+I)
// CTA tile 128x64, BK=64, 8 warps (4m x 2n), warp tile 32x32, double-buffered.
// ---------------------------------------------------------------------------
#define ROWB 144
#define ASTG (128 * ROWB)
#define BSTG (64 * ROWB)
#define STG  (ASTG + BSTG)
#define GSMT (2 * STG)

__device__ __forceinline__ void ldmx4(uint32_t* r, uint32_t addr) {
    asm volatile("ldmatrix.sync.aligned.m8n8.x4.shared.b16 {%0,%1,%2,%3}, [%4];"
                 : "=r"(r[0]), "=r"(r[1]), "=r"(r[2]), "=r"(r[3]) : "r"(addr));
}
__device__ __forceinline__ void mma16816(float* c, const uint32_t* a,
                                         uint32_t b0, uint32_t b1) {
    asm volatile(
        "mma.sync.aligned.m16n8k16.row.col.f32.f16.f16.f32 "
        "{%0,%1,%2,%3}, {%4,%5,%6,%7}, {%8,%9}, {%0,%1,%2,%3};"
        : "+f"(c[0]), "+f"(c[1]), "+f"(c[2]), "+f"(c[3])
        : "r"(a[0]), "r"(a[1]), "r"(a[2]), "r"(a[3]), "r"(b0), "r"(b1));
}

__global__ void __launch_bounds__(256) gemm_h_kernel(
    const __half* __restrict__ Ahi, const __half* __restrict__ Alo,
    const __half* __restrict__ BThi, const __half* __restrict__ BTlo,
    const float* __restrict__ Cm, float* __restrict__ Dm, int nseg, int addI) {
    extern __shared__ char smem[];
    const int t = threadIdx.x;
    const int wid = t >> 5, lid = t & 31;
    const int m0 = blockIdx.y * 128, n0 = blockIdx.x * 64;
    const int wm = wid >> 1, wn = wid & 1;
    const int CMAX = nseg << 4;

    const __half* segA[3] = { Ahi, Alo, Ahi };
    const __half* segB[3] = { BThi, BThi, BTlo };

    const int lrow = (lid & 7) + ((lid >> 3) & 1) * 8;
    const int lkof = (lid >> 4) * 8;

    float acc[2][4][4];
#pragma unroll
    for (int i = 0; i < 2; i++)
#pragma unroll
        for (int j = 0; j < 4; j++)
#pragma unroll
            for (int e = 0; e < 4; e++) acc[i][j][e] = 0.0f;

    const uint32_t sbase = smem_u32(smem);

    // preload chunk 0
    {
        const __half* Ap = segA[0];
        const __half* Bp = segB[0];
        char* as = smem;
        char* bs = smem + ASTG;
#pragma unroll
        for (int i = 0; i < 4; i++) {
            int u = t + 256 * i, r = u >> 3, q = u & 7;
            *(uint4*)(as + r * ROWB + q * 16) =
                *(const uint4*)(Ap + (size_t)(m0 + r) * MSZ + q * 8);
        }
#pragma unroll
        for (int i = 0; i < 2; i++) {
            int u = t + 256 * i, r = u >> 3, q = u & 7;
            *(uint4*)(bs + r * ROWB + q * 16) =
                *(const uint4*)(Bp + (size_t)(n0 + r) * MSZ + q * 8);
        }
    }
    __syncthreads();

    for (int c = 0; c < CMAX; c++) {
        uint4 apre[4], bpre[2];
        if (c < CMAX - 1) {
            int cn = c + 1;
            const __half* Ap = segA[cn >> 4];
            const __half* Bp = segB[cn >> 4];
            int k0 = (cn & 15) * 64;
#pragma unroll
            for (int i = 0; i < 4; i++) {
                int u = t + 256 * i, r = u >> 3, q = u & 7;
                apre[i] = *(const uint4*)(Ap + (size_t)(m0 + r) * MSZ + k0 + q * 8);
            }
#pragma unroll
            for (int i = 0; i < 2; i++) {
                int u = t + 256 * i, r = u >> 3, q = u & 7;
                bpre[i] = *(const uint4*)(Bp + (size_t)(n0 + r) * MSZ + k0 + q * 8);
            }
        }

        const uint32_t sa = sbase + (c & 1) * STG;
        const uint32_t sb = sa + ASTG;
#pragma unroll
        for (int ks = 0; ks < 4; ks++) {
            uint32_t af[2][4], bf[2][4];
#pragma unroll
            for (int i = 0; i < 2; i++)
                ldmx4(af[i], sa + (uint32_t)((wm * 32 + i * 16 + lrow) * ROWB +
                                             (ks * 16 + lkof) * 2));
#pragma unroll
            for (int j2 = 0; j2 < 2; j2++)
                ldmx4(bf[j2], sb + (uint32_t)((wn * 32 + j2 * 16 + lrow) * ROWB +
                                              (ks * 16 + lkof) * 2));
#pragma unroll
            for (int i = 0; i < 2; i++)
#pragma unroll
                for (int j = 0; j < 4; j++)
                    mma16816(acc[i][j], af[i], bf[j >> 1][j & 1], bf[j >> 1][(j & 1) + 2]);
        }
        __syncthreads();

        if (c < CMAX - 1) {
            char* as = smem + ((c + 1) & 1) * STG;
            char* bs = as + ASTG;
#pragma unroll
            for (int i = 0; i < 4; i++) {
                int u = t + 256 * i, r = u >> 3, q = u & 7;
                *(uint4*)(as + r * ROWB + q * 16) = apre[i];
            }
#pragma unroll
            for (int i = 0; i < 2; i++) {
                int u = t + 256 * i, r = u >> 3, q = u & 7;
                *(uint4*)(bs + r * ROWB + q * 16) = bpre[i];
            }
        }
        __syncthreads();
    }

    const int g = lid >> 2, q = lid & 3;
#pragma unroll
    for (int i = 0; i < 2; i++) {
#pragma unroll
        for (int j = 0; j < 4; j++) {
            int r0 = m0 + wm * 32 + i * 16 + g;
            int r1 = r0 + 8;
            int cc = n0 + wn * 32 + j * 8 + q * 2;
            float2 v0 = make_float2(acc[i][j][0], acc[i][j][1]);
            float2 v1 = make_float2(acc[i][j][2], acc[i][j][3]);
            if (Cm) {
                float2 c0 = *(const float2*)&Cm[(size_t)r0 * MSZ + cc];
                float2 c1 = *(const float2*)&Cm[(size_t)r1 * MSZ + cc];
                v0.x += c0.x; v0.y += c0.y;
                v1.x += c1.x; v1.y += c1.y;
            }
            if (addI) {
                if (r0 == cc)     v0.x += 1.0f;
                if (r0 == cc + 1) v0.y += 1.0f;
                if (r1 == cc)     v1.x += 1.0f;
                if (r1 == cc + 1) v1.y += 1.0f;
            }
            *(float2*)&Dm[(size_t)r0 * MSZ + cc] = v0;
            *(float2*)&Dm[(size_t)r1 * MSZ + cc] = v1;
        }
    }
}

// ---------------------------------------------------------------------------
// sigma = mu + eps * exp(logstd)
// ---------------------------------------------------------------------------
__global__ void sigma_kernel(const float4* __restrict__ mu,
                             const float4* __restrict__ ls,
                             const float4* __restrict__ ep,
                             float4* __restrict__ out) {
    int i = blockIdx.x * blockDim.x + threadIdx.x;
    float4 m = mu[i], l = ls[i], e = ep[i];
    float4 r;
    r.x = m.x + e.x * expf(l.x);
    r.y = m.y + e.y * expf(l.y);
    r.z = m.z + e.z * expf(l.z);
    r.w = m.w + e.w * expf(l.w);
    out[i] = r;
}

// ---------------------------------------------------------------------------
// z[b] = S[idx[b],:][:,idx[b]] @ sigma[b]  (one CTA per batch), FFMA2 inner
// ---------------------------------------------------------------------------
#define ZSMEM ((NPER * NPER + NPER * DDIM + NPER) * 4)
__global__ void __launch_bounds__(256) z_kernel(
    const float* __restrict__ S, const float* __restrict__ sigma,
    const int* __restrict__ ridx, float* __restrict__ z) {
    extern __shared__ float zsm[];
    float* sub_s = zsm;
    float* sig_s = zsm + NPER * NPER;
    int*   rows  = (int*)(sig_s + NPER * DDIM);

    const int b = blockIdx.x;
    const int t = threadIdx.x;

    if (t < NPER) rows[t] = ridx[b * NPER + t];
    {
        const float4* sg = (const float4*)(sigma + (size_t)b * NPER * DDIM);
        float4* ss = (float4*)sig_s;
        for (int i = t; i < NPER * DDIM / 4; i += 256) ss[i] = sg[i];
    }
    __syncthreads();
    {
        const int tj  = t & 127;
        const int ti0 = (t >> 7) * 64;
        const int cj  = rows[tj];
#pragma unroll 4
        for (int ii = 0; ii < 64; ii++) {
            int i = ti0 + ii;
            sub_s[i * NPER + tj] = S[(size_t)rows[i] * MSZ + cj];
        }
    }
    __syncthreads();

    const int d4 = t & 15;
    const int ig = t >> 4;
    unsigned long long accA[8], accB[8];
#pragma unroll
    for (int r = 0; r < 8; r++) { accA[r] = 0ull; accB[r] = 0ull; }

    const float4* sig4 = (const float4*)sig_s;
    for (int j = 0; j < NPER; j++) {
        float4 sv = sig4[j * (DDIM / 4) + d4];
        unsigned long long sxy = pack2(sv.x, sv.y);
        unsigned long long szw = pack2(sv.z, sv.w);
#pragma unroll
        for (int r = 0; r < 8; r++) {
            float a = sub_s[(ig * 8 + r) * NPER + j];
            unsigned long long aa = pack2(a, a);
            fma2(accA[r], aa, sxy);
            fma2(accB[r], aa, szw);
        }
    }
    float4* zp = (float4*)(z + (size_t)b * NPER * DDIM);
#pragma unroll
    for (int r = 0; r < 8; r++) {
        float4 v;
        unpack2(accA[r], v.x, v.y);
        unpack2(accB[r], v.z, v.w);
        zp[(ig * 8 + r) * (DDIM / 4) + d4] = v;
    }
}

// ---------------------------------------------------------------------------
// kernel_launch — order-16 Neumann: S = (I+X)(I+X2)(I+X4)(I+X8)
// ---------------------------------------------------------------------------
extern "C" void kernel_launch(void* const* d_in, const int* in_sizes, int n_in,
                              void* d_out, int out_size) {
    const float* A      = (const float*)d_in[0];
    const float* mu     = (const float*)d_in[1];
    const float* logstd = (const float*)d_in[2];
    const float* eps    = (const float*)d_in[3];
    const void*  nidx   = d_in[4];

    float* out_sigma = (float*)d_out;
    float* out_z     = out_sigma + SIGN;

    float* bufs = nullptr;
    cudaGetSymbolAddress((void**)&bufs, g_scratch);
    __half* hfb = nullptr;
    cudaGetSymbolAddress((void**)&hfb, g_hf);
    int* rows_dev = nullptr;
    cudaGetSymbolAddress((void**)&rows_dev, g_rows);

    float* BX   = bufs + 0 * M2;  // X
    float* BX2  = bufs + 1 * M2;  // X2 -> Q2
    float* BX4  = bufs + 2 * M2;  // X4
    float* BX8  = bufs + 3 * M2;  // X8
    float* BQ1  = bufs + 5 * M2;  // Q1 -> S

    auto Q = [&](int q, int p) { return hfb + ((size_t)(q * 4 + p)) * M2; };

    dim3 gT(MSZ / 32, MSZ / 32), bT(32, 8);
    dim3 gG(MSZ / 64, MSZ / 128);   // (16, 8) = 128 CTAs

    cudaFuncSetAttribute(gemm_h_kernel, cudaFuncAttributeMaxDynamicSharedMemorySize, GSMT);
    cudaFuncSetAttribute(z_kernel, cudaFuncAttributeMaxDynamicSharedMemorySize, ZSMEM);

    idx_detect_kernel<<<1, 256>>>((const unsigned int*)nidx);
    idx_convert_kernel<<<NIDX / 256, 256>>>(nidx);

#define GEMM_T(qa, qb, Cp, Dp, ns, ai) \
    gemm_h_kernel<<<gG, 256, GSMT>>>(Q(qa,0), Q(qa,1), Q(qb,2), Q(qb,3), Cp, Dp, ns, ai)
#define CVT(Rp, q, ai) \
    cvt_kernel<<<gT, bT>>>(Rp, Q(q,0), Q(q,1), Q(q,2), Q(q,3), ai)

    transpose_kernel<<<gT, bT>>>(A, BX);              // X = A^T
    CVT(BX, 0, 0);                                    // q0 = X
    GEMM_T(0, 0, (const float*)nullptr, BX2, 1, 0);   // X2 = X*X         (plain)
    CVT(BX, 2, 1);                                    // q2 = P1 = I+X
    CVT(BX2, 1, 0);                                   // q1 = X2
    GEMM_T(1, 1, (const float*)nullptr, BX4, 1, 0);   // X4 = X2*X2       (plain)
    GEMM_T(2, 1, BX, BQ1, 1, 1);                      // Q1 = P1*X2 + X + I (plain)
    CVT(BX4, 3, 0);                                   // q3 = X4
    GEMM_T(3, 3, (const float*)nullptr, BX8, 1, 0);   // X8 = X4*X4       (plain)
    CVT(BX4, 4, 1);                                   // q4 = P4 = I+X4
    CVT(BX8, 5, 0);                                   // q5 = X8
    GEMM_T(4, 5, BX4, BX2, 1, 1);                     // Q2 = P4*X8 + X4 + I (plain)
    CVT(BQ1, 0, 0);                                   // q0 = Q1
    CVT(BX2, 1, 0);                                   // q1 = Q2
    GEMM_T(0, 1, (const float*)nullptr, BQ1, 3, 0);   // S = Q1*Q2        (SPLIT)

    sigma_kernel<<<SIGN / 4 / 256, 256>>>((const float4*)mu, (const float4*)logstd,
                                          (const float4*)eps, (float4*)out_sigma);

    z_kernel<<<NBAT, 256, ZSMEM>>>(BQ1, out_sigma, rows_dev, out_z);
#undef GEMM_T
#undef CVT
}

// round 9
// speedup vs baseline: 2.5060x; 1.1402x over previous
#include <cuda_runtime.h>
#include <cuda_bf16.h>
#include <cuda_fp16.h>
#include <math.h>
#include <stdint.h>

#define MSZ   1024
#define M2    (MSZ * MSZ)
#define NPER  128
#define DDIM  64
#define NBAT  2048
#define NIDX  (NBAT * NPER)          // 262144
#define SIGN  (NBAT * NPER * DDIM)   // 16777216

// f32 scratch (6 x 4MB) + f16 planes (8 pairs hi/lo = 16 planes x 2MB)
__device__ float g_scratch[6 * M2];
__device__ __half g_hf[16 * M2];
__device__ int g_rows[NIDX];
__device__ unsigned int g_odd_or;

__device__ __forceinline__ uint32_t smem_u32(const void* p) {
    uint32_t a;
    asm("{ .reg .u64 t; cvta.to.shared.u64 t, %1; cvt.u32.u64 %0, t; }" : "=r"(a) : "l"(p));
    return a;
}
// f32x2 packed helpers
__device__ __forceinline__ unsigned long long pack2(float x, float y) {
    unsigned long long r;
    asm("mov.b64 %0, {%1, %2};" : "=l"(r) : "f"(x), "f"(y));
    return r;
}
__device__ __forceinline__ void fma2(unsigned long long& d,
                                     unsigned long long a, unsigned long long b) {
    asm("fma.rn.f32x2 %0, %1, %2, %0;" : "+l"(d) : "l"(a), "l"(b));
}
__device__ __forceinline__ void unpack2(unsigned long long v, float& lo, float& hi) {
    asm("mov.b64 {%0, %1}, %2;" : "=f"(lo), "=f"(hi) : "l"(v));
}

// ---------------------------------------------------------------------------
// Index dtype detection + conversion (int64 vs int32 harness layout)
// ---------------------------------------------------------------------------
__global__ void idx_detect_kernel(const unsigned int* __restrict__ v32) {
    __shared__ unsigned int s[256];
    unsigned int o = 0;
    for (int i = threadIdx.x; i < NIDX / 2; i += 256) o |= v32[2 * i + 1];
    s[threadIdx.x] = o;
    __syncthreads();
    for (int d = 128; d > 0; d >>= 1) {
        if (threadIdx.x < d) s[threadIdx.x] |= s[threadIdx.x + d];
        __syncthreads();
    }
    if (threadIdx.x == 0) g_odd_or = s[0];
}
__global__ void idx_convert_kernel(const void* __restrict__ raw) {
    int i = blockIdx.x * blockDim.x + threadIdx.x;
    if (i >= NIDX) return;
    g_rows[i] = (g_odd_or == 0u) ? (int)((const long long*)raw)[i]
                                 : ((const int*)raw)[i];
}

// ---------------------------------------------------------------------------
// Transpose + split: T = A^T (f32), plus f16 planes of X and of P1 = I+X
// ---------------------------------------------------------------------------
__global__ void transpose_cvt_kernel(const float* __restrict__ A, float* __restrict__ T,
                                     __half* __restrict__ xh, __half* __restrict__ xl,
                                     __half* __restrict__ ph, __half* __restrict__ pl) {
    __shared__ float tile[32][33];
    int x = blockIdx.x * 32 + threadIdx.x;
    int y = blockIdx.y * 32 + threadIdx.y;
#pragma unroll
    for (int j = 0; j < 32; j += 8)
        tile[threadIdx.y + j][threadIdx.x] = A[(y + j) * MSZ + x];
    __syncthreads();
    int xT = blockIdx.y * 32 + threadIdx.x;
    int yT0 = blockIdx.x * 32 + threadIdx.y;
#pragma unroll
    for (int j = 0; j < 32; j += 8) {
        int yT = yT0 + j;
        float v = tile[threadIdx.x][threadIdx.y + j];
        size_t o = (size_t)yT * MSZ + xT;
        T[o] = v;
        __half h = __float2half_rn(v);
        xh[o] = h;
        xl[o] = __float2half_rn(v - __half2float(h));
        float w = v + ((yT == xT) ? 1.0f : 0.0f);
        __half hw = __float2half_rn(w);
        ph[o] = hw;
        pl[o] = __float2half_rn(w - __half2float(hw));
    }
}

// ---------------------------------------------------------------------------
// Tensor-core f16 GEMM via mma.sync with fused split-emit epilogue.
//   nseg=1: D = Ah*Bh (+C) (+I);  nseg=3: + Al*Bh + Ah*Bl
// A planes row-major [m][k]; B planes row-major [k][n] (ldmatrix.trans).
// Epilogue: writes D f32; optionally f16 hi/lo planes of D (Eh/El) and of
// D+I (Fh/Fl).
// CTA tile 128x64, BK=64, 8 warps (4m x 2n), double-buffered.
// ---------------------------------------------------------------------------
#define ROWB 144
#define ASTG (128 * ROWB)
#define BSTG (64 * ROWB)
#define STG  (ASTG + BSTG)
#define GSMT (2 * STG)

__device__ __forceinline__ void ldmx4(uint32_t* r, uint32_t addr) {
    asm volatile("ldmatrix.sync.aligned.m8n8.x4.shared.b16 {%0,%1,%2,%3}, [%4];"
                 : "=r"(r[0]), "=r"(r[1]), "=r"(r[2]), "=r"(r[3]) : "r"(addr));
}
__device__ __forceinline__ void ldmx4t(uint32_t* r, uint32_t addr) {
    asm volatile("ldmatrix.sync.aligned.m8n8.x4.trans.shared.b16 {%0,%1,%2,%3}, [%4];"
                 : "=r"(r[0]), "=r"(r[1]), "=r"(r[2]), "=r"(r[3]) : "r"(addr));
}
__device__ __forceinline__ void mma16816(float* c, const uint32_t* a,
                                         uint32_t b0, uint32_t b1) {
    asm volatile(
        "mma.sync.aligned.m16n8k16.row.col.f32.f16.f16.f32 "
        "{%0,%1,%2,%3}, {%4,%5,%6,%7}, {%8,%9}, {%0,%1,%2,%3};"
        : "+f"(c[0]), "+f"(c[1]), "+f"(c[2]), "+f"(c[3])
        : "r"(a[0]), "r"(a[1]), "r"(a[2]), "r"(a[3]), "r"(b0), "r"(b1));
}
__device__ __forceinline__ void emit_pair(__half* __restrict__ H, __half* __restrict__ L,
                                          size_t o, float2 v) {
    __half2 h = __floats2half2_rn(v.x, v.y);
    *(__half2*)&H[o] = h;
    float2 r = make_float2(v.x - __half2float(__low2half(h)),
                           v.y - __half2float(__high2half(h)));
    *(__half2*)&L[o] = __floats2half2_rn(r.x, r.y);
}

__global__ void __launch_bounds__(256) gemm_h_kernel(
    const __half* __restrict__ Ah, const __half* __restrict__ Al,
    const __half* __restrict__ Bh, const __half* __restrict__ Bl,
    const float* __restrict__ Cm, float* __restrict__ Dm, int nseg, int addI,
    __half* __restrict__ Eh, __half* __restrict__ El,
    __half* __restrict__ Fh, __half* __restrict__ Fl) {
    extern __shared__ char smem[];
    const int t = threadIdx.x;
    const int wid = t >> 5, lid = t & 31;
    const int m0 = blockIdx.y * 128, n0 = blockIdx.x * 64;
    const int wm = wid >> 1, wn = wid & 1;
    const int CMAX = nseg << 4;

    const __half* segA[3] = { Ah, Al, Ah };
    const __half* segB[3] = { Bh, Bh, Bl };

    const int lrow = (lid & 7) + ((lid >> 3) & 1) * 8;  // A-frag row sel
    const int lkof = (lid >> 4) * 8;                    // A-frag k sel
    const int bkr  = lid & 15;                          // B-frag k row
    const int bnof = (lid >> 4) * 8;                    // B-frag n sel

    float acc[2][4][4];
#pragma unroll
    for (int i = 0; i < 2; i++)
#pragma unroll
        for (int j = 0; j < 4; j++)
#pragma unroll
            for (int e = 0; e < 4; e++) acc[i][j][e] = 0.0f;

    const uint32_t sbase = smem_u32(smem);

    // preload chunk 0: A rows m, B rows k
    {
        char* as = smem;
        char* bs = smem + ASTG;
#pragma unroll
        for (int i = 0; i < 4; i++) {
            int u = t + 256 * i, r = u >> 3, q = u & 7;
            *(uint4*)(as + r * ROWB + q * 16) =
                *(const uint4*)(segA[0] + (size_t)(m0 + r) * MSZ + q * 8);
        }
#pragma unroll
        for (int i = 0; i < 2; i++) {
            int u = t + 256 * i, r = u >> 3, q = u & 7;
            *(uint4*)(bs + r * ROWB + q * 16) =
                *(const uint4*)(segB[0] + (size_t)r * MSZ + n0 + q * 8);
        }
    }
    __syncthreads();

    for (int c = 0; c < CMAX; c++) {
        uint4 apre[4], bpre[2];
        if (c < CMAX - 1) {
            int cn = c + 1;
            const __half* Ap = segA[cn >> 4];
            const __half* Bp = segB[cn >> 4];
            int k0 = (cn & 15) * 64;
#pragma unroll
            for (int i = 0; i < 4; i++) {
                int u = t + 256 * i, r = u >> 3, q = u & 7;
                apre[i] = *(const uint4*)(Ap + (size_t)(m0 + r) * MSZ + k0 + q * 8);
            }
#pragma unroll
            for (int i = 0; i < 2; i++) {
                int u = t + 256 * i, r = u >> 3, q = u & 7;
                bpre[i] = *(const uint4*)(Bp + (size_t)(k0 + r) * MSZ + n0 + q * 8);
            }
        }

        const uint32_t sa = sbase + (c & 1) * STG;
        const uint32_t sb = sa + ASTG;
#pragma unroll
        for (int ks = 0; ks < 4; ks++) {
            uint32_t af[2][4], bf[2][4];
#pragma unroll
            for (int i = 0; i < 2; i++)
                ldmx4(af[i], sa + (uint32_t)((wm * 32 + i * 16 + lrow) * ROWB +
                                             (ks * 16 + lkof) * 2));
#pragma unroll
            for (int j2 = 0; j2 < 2; j2++)
                ldmx4t(bf[j2], sb + (uint32_t)((ks * 16 + bkr) * ROWB +
                                               (wn * 32 + j2 * 16 + bnof) * 2));
#pragma unroll
            for (int i = 0; i < 2; i++)
#pragma unroll
                for (int j = 0; j < 4; j++)
                    mma16816(acc[i][j], af[i], bf[j >> 1][2 * (j & 1)],
                             bf[j >> 1][2 * (j & 1) + 1]);
        }
        __syncthreads();

        if (c < CMAX - 1) {
            char* as = smem + ((c + 1) & 1) * STG;
            char* bs = as + ASTG;
#pragma unroll
            for (int i = 0; i < 4; i++) {
                int u = t + 256 * i, r = u >> 3, q = u & 7;
                *(uint4*)(as + r * ROWB + q * 16) = apre[i];
            }
#pragma unroll
            for (int i = 0; i < 2; i++) {
                int u = t + 256 * i, r = u >> 3, q = u & 7;
                *(uint4*)(bs + r * ROWB + q * 16) = bpre[i];
            }
        }
        __syncthreads();
    }

    const int g = lid >> 2, q = lid & 3;
#pragma unroll
    for (int i = 0; i < 2; i++) {
#pragma unroll
        for (int j = 0; j < 4; j++) {
            int r0 = m0 + wm * 32 + i * 16 + g;
            int r1 = r0 + 8;
            int cc = n0 + wn * 32 + j * 8 + q * 2;
            float2 v0 = make_float2(acc[i][j][0], acc[i][j][1]);
            float2 v1 = make_float2(acc[i][j][2], acc[i][j][3]);
            if (Cm) {
                float2 c0 = *(const float2*)&Cm[(size_t)r0 * MSZ + cc];
                float2 c1 = *(const float2*)&Cm[(size_t)r1 * MSZ + cc];
                v0.x += c0.x; v0.y += c0.y;
                v1.x += c1.x; v1.y += c1.y;
            }
            if (addI) {
                if (r0 == cc)     v0.x += 1.0f;
                if (r0 == cc + 1) v0.y += 1.0f;
                if (r1 == cc)     v1.x += 1.0f;
                if (r1 == cc + 1) v1.y += 1.0f;
            }
            size_t o0 = (size_t)r0 * MSZ + cc, o1 = (size_t)r1 * MSZ + cc;
            *(float2*)&Dm[o0] = v0;
            *(float2*)&Dm[o1] = v1;
            if (Eh) { emit_pair(Eh, El, o0, v0); emit_pair(Eh, El, o1, v1); }
            if (Fh) {
                float2 w0 = v0, w1 = v1;
                if (r0 == cc)     w0.x += 1.0f;
                if (r0 == cc + 1) w0.y += 1.0f;
                if (r1 == cc)     w1.x += 1.0f;
                if (r1 == cc + 1) w1.y += 1.0f;
                emit_pair(Fh, Fl, o0, w0); emit_pair(Fh, Fl, o1, w1);
            }
        }
    }
}

// ---------------------------------------------------------------------------
// Fused sigma + z:
//   sigma = mu + eps*exp(logstd)  (computed per batch tile, written to out)
//   z[b]  = S[idx[b],:][:,idx[b]] @ sigma[b]
// ---------------------------------------------------------------------------
#define ZSMEM ((NPER * NPER + NPER * DDIM + NPER) * 4)
__global__ void __launch_bounds__(256) z_kernel(
    const float* __restrict__ S,
    const float4* __restrict__ mu, const float4* __restrict__ ls,
    const float4* __restrict__ ep,
    const int* __restrict__ ridx,
    float4* __restrict__ out_sigma, float* __restrict__ z) {
    extern __shared__ float zsm[];
    float* sub_s = zsm;
    float* sig_s = zsm + NPER * NPER;
    int*   rows  = (int*)(sig_s + NPER * DDIM);

    const int b = blockIdx.x;
    const int t = threadIdx.x;

    if (t < NPER) rows[t] = ridx[b * NPER + t];
    {
        const size_t base = (size_t)b * (NPER * DDIM / 4);
        float4* ss = (float4*)sig_s;
        for (int i = t; i < NPER * DDIM / 4; i += 256) {
            float4 m = mu[base + i], l = ls[base + i], e = ep[base + i];
            float4 r;
            r.x = m.x + e.x * expf(l.x);
            r.y = m.y + e.y * expf(l.y);
            r.z = m.z + e.z * expf(l.z);
            r.w = m.w + e.w * expf(l.w);
            ss[i] = r;
            out_sigma[base + i] = r;
        }
    }
    __syncthreads();
    {
        const int tj  = t & 127;
        const int ti0 = (t >> 7) * 64;
        const int cj  = rows[tj];
#pragma unroll 4
        for (int ii = 0; ii < 64; ii++) {
            int i = ti0 + ii;
            sub_s[i * NPER + tj] = S[(size_t)rows[i] * MSZ + cj];
        }
    }
    __syncthreads();

    const int d4 = t & 15;
    const int ig = t >> 4;
    unsigned long long accA[8], accB[8];
#pragma unroll
    for (int r = 0; r < 8; r++) { accA[r] = 0ull; accB[r] = 0ull; }

    const float4* sig4 = (const float4*)sig_s;
    for (int j = 0; j < NPER; j++) {
        float4 sv = sig4[j * (DDIM / 4) + d4];
        unsigned long long sxy = pack2(sv.x, sv.y);
        unsigned long long szw = pack2(sv.z, sv.w);
#pragma unroll
        for (int r = 0; r < 8; r++) {
            float a = sub_s[(ig * 8 + r) * NPER + j];
            unsigned long long aa = pack2(a, a);
            fma2(accA[r], aa, sxy);
            fma2(accB[r], aa, szw);
        }
    }
    float4* zp = (float4*)(z + (size_t)b * NPER * DDIM);
#pragma unroll
    for (int r = 0; r < 8; r++) {
        float4 v;
        unpack2(accA[r], v.x, v.y);
        unpack2(accB[r], v.z, v.w);
        zp[(ig * 8 + r) * (DDIM / 4) + d4] = v;
    }
}

// ---------------------------------------------------------------------------
// kernel_launch — order-16 Neumann: S = (I+X)(I+X2)(I+X4)(I+X8)
// ---------------------------------------------------------------------------
extern "C" void kernel_launch(void* const* d_in, const int* in_sizes, int n_in,
                              void* d_out, int out_size) {
    const float* A      = (const float*)d_in[0];
    const float* mu     = (const float*)d_in[1];
    const float* logstd = (const float*)d_in[2];
    const float* eps    = (const float*)d_in[3];
    const void*  nidx   = d_in[4];

    float* out_sigma = (float*)d_out;
    float* out_z     = out_sigma + SIGN;

    float* bufs = nullptr;
    cudaGetSymbolAddress((void**)&bufs, g_scratch);
    __half* hfb = nullptr;
    cudaGetSymbolAddress((void**)&hfb, g_hf);
    int* rows_dev = nullptr;
    cudaGetSymbolAddress((void**)&rows_dev, g_rows);

    float* BX   = bufs + 0 * M2;  // X
    float* BX2  = bufs + 1 * M2;  // X2 -> Q2
    float* BX4  = bufs + 2 * M2;  // X4
    float* BX8  = bufs + 3 * M2;  // X8
    float* BQ1  = bufs + 5 * M2;  // Q1 -> S

    // plane pair p: hi = P(p,0), lo = P(p,1)
    auto P = [&](int p, int hl) { return hfb + ((size_t)(p * 2 + hl)) * M2; };
    __half* NUL = nullptr;

    dim3 gT(MSZ / 32, MSZ / 32), bT(32, 8);
    dim3 gG(MSZ / 64, MSZ / 128);   // (16, 8) = 128 CTAs

    cudaFuncSetAttribute(gemm_h_kernel, cudaFuncAttributeMaxDynamicSharedMemorySize, GSMT);
    cudaFuncSetAttribute(z_kernel, cudaFuncAttributeMaxDynamicSharedMemorySize, ZSMEM);

    idx_detect_kernel<<<1, 256>>>((const unsigned int*)nidx);
    idx_convert_kernel<<<NIDX / 256, 256>>>(nidx);

#define GEMM_T(pa, pb, Cp, Dp, ns, ai, pe, pf) \
    gemm_h_kernel<<<gG, 256, GSMT>>>(P(pa,0), P(pa,1), P(pb,0), P(pb,1), Cp, Dp, ns, ai, \
        (pe) < 0 ? NUL : P(pe,0), (pe) < 0 ? NUL : P(pe,1), \
        (pf) < 0 ? NUL : P(pf,0), (pf) < 0 ? NUL : P(pf,1))

    // pairs: 0=X 1=P1 2=X2 3=X4 4=P4 5=Q1 6=X8 7=Q2
    transpose_cvt_kernel<<<gT, bT>>>(A, BX, P(0,0), P(0,1), P(1,0), P(1,1));
    GEMM_T(0, 0, (const float*)nullptr, BX2, 1, 0, 2, -1);  // X2 = X*X, emit X2
    GEMM_T(2, 2, (const float*)nullptr, BX4, 1, 0, 3, 4);   // X4 = X2*X2, emit X4 + P4
    GEMM_T(1, 2, BX, BQ1, 1, 1, 5, -1);                     // Q1 = P1*X2 + X + I, emit Q1
    GEMM_T(3, 3, (const float*)nullptr, BX8, 1, 0, 6, -1);  // X8 = X4*X4, emit X8
    GEMM_T(4, 6, BX4, BX2, 1, 1, 7, -1);                    // Q2 = P4*X8 + X4 + I, emit Q2
    GEMM_T(5, 7, (const float*)nullptr, BQ1, 3, 0, -1, -1); // S = Q1*Q2 (SPLIT)

    z_kernel<<<NBAT, 256, ZSMEM>>>(BQ1, (const float4*)mu, (const float4*)logstd,
                                   (const float4*)eps, rows_dev,
                                   (float4*)out_sigma, out_z);
#undef GEMM_T
}

// round 10
// speedup vs baseline: 2.8330x; 1.1305x over previous
#include <cuda_runtime.h>
#include <cuda_bf16.h>
#include <cuda_fp16.h>
#include <math.h>
#include <stdint.h>

#define MSZ   1024
#define M2    (MSZ * MSZ)
#define NPER  128
#define DDIM  64
#define NBAT  2048
#define NIDX  (NBAT * NPER)          // 262144
#define SIGN  (NBAT * NPER * DDIM)   // 16777216

// f32 scratch (6 x 4MB) + f16 planes (8 pairs hi/lo = 16 planes x 2MB)
__device__ float g_scratch[6 * M2];
__device__ __half g_hf[16 * M2];
__device__ int g_rows[NIDX];
__device__ unsigned int g_odd_or;

__device__ __forceinline__ uint32_t smem_u32(const void* p) {
    uint32_t a;
    asm("{ .reg .u64 t; cvta.to.shared.u64 t, %1; cvt.u32.u64 %0, t; }" : "=r"(a) : "l"(p));
    return a;
}
// f32x2 packed helpers
__device__ __forceinline__ unsigned long long pack2(float x, float y) {
    unsigned long long r;
    asm("mov.b64 %0, {%1, %2};" : "=l"(r) : "f"(x), "f"(y));
    return r;
}
__device__ __forceinline__ void fma2(unsigned long long& d,
                                     unsigned long long a, unsigned long long b) {
    asm("fma.rn.f32x2 %0, %1, %2, %0;" : "+l"(d) : "l"(a), "l"(b));
}
__device__ __forceinline__ void unpack2(unsigned long long v, float& lo, float& hi) {
    asm("mov.b64 {%0, %1}, %2;" : "=f"(lo), "=f"(hi) : "l"(v));
}

// ---------------------------------------------------------------------------
// Index dtype detection + conversion (int64 vs int32 harness layout)
// ---------------------------------------------------------------------------
__global__ void idx_detect_kernel(const unsigned int* __restrict__ v32) {
    __shared__ unsigned int s[256];
    unsigned int o = 0;
    for (int i = threadIdx.x; i < NIDX / 2; i += 256) o |= v32[2 * i + 1];
    s[threadIdx.x] = o;
    __syncthreads();
    for (int d = 128; d > 0; d >>= 1) {
        if (threadIdx.x < d) s[threadIdx.x] |= s[threadIdx.x + d];
        __syncthreads();
    }
    if (threadIdx.x == 0) g_odd_or = s[0];
}
__global__ void idx_convert_kernel(const void* __restrict__ raw) {
    int i = blockIdx.x * blockDim.x + threadIdx.x;
    if (i >= NIDX) return;
    g_rows[i] = (g_odd_or == 0u) ? (int)((const long long*)raw)[i]
                                 : ((const int*)raw)[i];
}

// ---------------------------------------------------------------------------
// Transpose + split: T = A^T (f32), plus f16 planes of X and of P1 = I+X
// ---------------------------------------------------------------------------
__global__ void transpose_cvt_kernel(const float* __restrict__ A, float* __restrict__ T,
                                     __half* __restrict__ xh, __half* __restrict__ xl,
                                     __half* __restrict__ ph, __half* __restrict__ pl) {
    __shared__ float tile[32][33];
    int x = blockIdx.x * 32 + threadIdx.x;
    int y = blockIdx.y * 32 + threadIdx.y;
#pragma unroll
    for (int j = 0; j < 32; j += 8)
        tile[threadIdx.y + j][threadIdx.x] = A[(y + j) * MSZ + x];
    __syncthreads();
    int xT = blockIdx.y * 32 + threadIdx.x;
    int yT0 = blockIdx.x * 32 + threadIdx.y;
#pragma unroll
    for (int j = 0; j < 32; j += 8) {
        int yT = yT0 + j;
        float v = tile[threadIdx.x][threadIdx.y + j];
        size_t o = (size_t)yT * MSZ + xT;
        T[o] = v;
        __half h = __float2half_rn(v);
        xh[o] = h;
        xl[o] = __float2half_rn(v - __half2float(h));
        float w = v + ((yT == xT) ? 1.0f : 0.0f);
        __half hw = __float2half_rn(w);
        ph[o] = hw;
        pl[o] = __float2half_rn(w - __half2float(hw));
    }
}

// ---------------------------------------------------------------------------
// Tensor-core f16 GEMM via mma.sync with fused split-emit epilogue.
//   nseg=1: D = Ah*Bh (+C) (+I);  nseg=3: + Al*Bh + Ah*Bl
// A planes row-major [m][k]; B planes row-major [k][n] (ldmatrix.trans).
// CTA tile 64x64, BK=64, 4 warps (2m x 2n), warp tile 32x32,
// double-buffered with ONE barrier per chunk. Grid (16,16)=256 -> 2 CTAs/SM.
// ---------------------------------------------------------------------------
#define ROWB 144
#define ASTG (64 * ROWB)
#define BSTG (64 * ROWB)
#define STG  (ASTG + BSTG)
#define GSMT (2 * STG)

__device__ __forceinline__ void ldmx4(uint32_t* r, uint32_t addr) {
    asm volatile("ldmatrix.sync.aligned.m8n8.x4.shared.b16 {%0,%1,%2,%3}, [%4];"
                 : "=r"(r[0]), "=r"(r[1]), "=r"(r[2]), "=r"(r[3]) : "r"(addr));
}
__device__ __forceinline__ void ldmx4t(uint32_t* r, uint32_t addr) {
    asm volatile("ldmatrix.sync.aligned.m8n8.x4.trans.shared.b16 {%0,%1,%2,%3}, [%4];"
                 : "=r"(r[0]), "=r"(r[1]), "=r"(r[2]), "=r"(r[3]) : "r"(addr));
}
__device__ __forceinline__ void mma16816(float* c, const uint32_t* a,
                                         uint32_t b0, uint32_t b1) {
    asm volatile(
        "mma.sync.aligned.m16n8k16.row.col.f32.f16.f16.f32 "
        "{%0,%1,%2,%3}, {%4,%5,%6,%7}, {%8,%9}, {%0,%1,%2,%3};"
        : "+f"(c[0]), "+f"(c[1]), "+f"(c[2]), "+f"(c[3])
        : "r"(a[0]), "r"(a[1]), "r"(a[2]), "r"(a[3]), "r"(b0), "r"(b1));
}
__device__ __forceinline__ void emit_pair(__half* __restrict__ H, __half* __restrict__ L,
                                          size_t o, float2 v) {
    __half2 h = __floats2half2_rn(v.x, v.y);
    *(__half2*)&H[o] = h;
    float2 r = make_float2(v.x - __half2float(__low2half(h)),
                           v.y - __half2float(__high2half(h)));
    *(__half2*)&L[o] = __floats2half2_rn(r.x, r.y);
}

__global__ void __launch_bounds__(128) gemm_h_kernel(
    const __half* __restrict__ Ah, const __half* __restrict__ Al,
    const __half* __restrict__ Bh, const __half* __restrict__ Bl,
    const float* __restrict__ Cm, float* __restrict__ Dm, int nseg, int addI,
    __half* __restrict__ Eh, __half* __restrict__ El,
    __half* __restrict__ Fh, __half* __restrict__ Fl) {
    extern __shared__ char smem[];
    const int t = threadIdx.x;
    const int wid = t >> 5, lid = t & 31;
    const int m0 = blockIdx.y * 64, n0 = blockIdx.x * 64;
    const int wm = wid >> 1, wn = wid & 1;
    const int CMAX = nseg << 4;

    const __half* segA[3] = { Ah, Al, Ah };
    const __half* segB[3] = { Bh, Bh, Bl };

    const int lrow = (lid & 7) + ((lid >> 3) & 1) * 8;  // A-frag row sel
    const int lkof = (lid >> 4) * 8;                    // A-frag k sel
    const int bkr  = lid & 15;                          // B-frag k row
    const int bnof = (lid >> 4) * 8;                    // B-frag n sel

    float acc[2][4][4];
#pragma unroll
    for (int i = 0; i < 2; i++)
#pragma unroll
        for (int j = 0; j < 4; j++)
#pragma unroll
            for (int e = 0; e < 4; e++) acc[i][j][e] = 0.0f;

    const uint32_t sbase = smem_u32(smem);

    // preload chunk 0: A rows m (64x64 halves), B rows k (64x64 halves)
    {
        char* as = smem;
        char* bs = smem + ASTG;
#pragma unroll
        for (int i = 0; i < 4; i++) {
            int u = t + 128 * i, r = u >> 3, q = u & 7;
            *(uint4*)(as + r * ROWB + q * 16) =
                *(const uint4*)(segA[0] + (size_t)(m0 + r) * MSZ + q * 8);
            *(uint4*)(bs + r * ROWB + q * 16) =
                *(const uint4*)(segB[0] + (size_t)r * MSZ + n0 + q * 8);
        }
    }
    __syncthreads();

    for (int c = 0; c < CMAX; c++) {
        uint4 apre[4], bpre[4];
        if (c < CMAX - 1) {
            int cn = c + 1;
            const __half* Ap = segA[cn >> 4];
            const __half* Bp = segB[cn >> 4];
            int k0 = (cn & 15) * 64;
#pragma unroll
            for (int i = 0; i < 4; i++) {
                int u = t + 128 * i, r = u >> 3, q = u & 7;
                apre[i] = *(const uint4*)(Ap + (size_t)(m0 + r) * MSZ + k0 + q * 8);
                bpre[i] = *(const uint4*)(Bp + (size_t)(k0 + r) * MSZ + n0 + q * 8);
            }
        }

        const uint32_t sa = sbase + (c & 1) * STG;
        const uint32_t sb = sa + ASTG;
#pragma unroll
        for (int ks = 0; ks < 4; ks++) {
            uint32_t af[2][4], bf[2][4];
#pragma unroll
            for (int i = 0; i < 2; i++)
                ldmx4(af[i], sa + (uint32_t)((wm * 32 + i * 16 + lrow) * ROWB +
                                             (ks * 16 + lkof) * 2));
#pragma unroll
            for (int j2 = 0; j2 < 2; j2++)
                ldmx4t(bf[j2], sb + (uint32_t)((ks * 16 + bkr) * ROWB +
                                               (wn * 32 + j2 * 16 + bnof) * 2));
#pragma unroll
            for (int i = 0; i < 2; i++)
#pragma unroll
                for (int j = 0; j < 4; j++)
                    mma16816(acc[i][j], af[i], bf[j >> 1][2 * (j & 1)],
                             bf[j >> 1][2 * (j & 1) + 1]);
        }

        if (c < CMAX - 1) {
            // stores target the OTHER buffer; current compute already read from
            // this one, so a single end-of-chunk barrier covers both hazards
            char* as = smem + ((c + 1) & 1) * STG;
            char* bs = as + ASTG;
#pragma unroll
            for (int i = 0; i < 4; i++) {
                int u = t + 128 * i, r = u >> 3, q = u & 7;
                *(uint4*)(as + r * ROWB + q * 16) = apre[i];
                *(uint4*)(bs + r * ROWB + q * 16) = bpre[i];
            }
            __syncthreads();
        }
    }

    const int g = lid >> 2, q = lid & 3;
#pragma unroll
    for (int i = 0; i < 2; i++) {
#pragma unroll
        for (int j = 0; j < 4; j++) {
            int r0 = m0 + wm * 32 + i * 16 + g;
            int r1 = r0 + 8;
            int cc = n0 + wn * 32 + j * 8 + q * 2;
            float2 v0 = make_float2(acc[i][j][0], acc[i][j][1]);
            float2 v1 = make_float2(acc[i][j][2], acc[i][j][3]);
            if (Cm) {
                float2 c0 = *(const float2*)&Cm[(size_t)r0 * MSZ + cc];
                float2 c1 = *(const float2*)&Cm[(size_t)r1 * MSZ + cc];
                v0.x += c0.x; v0.y += c0.y;
                v1.x += c1.x; v1.y += c1.y;
            }
            if (addI) {
                if (r0 == cc)     v0.x += 1.0f;
                if (r0 == cc + 1) v0.y += 1.0f;
                if (r1 == cc)     v1.x += 1.0f;
                if (r1 == cc + 1) v1.y += 1.0f;
            }
            size_t o0 = (size_t)r0 * MSZ + cc, o1 = (size_t)r1 * MSZ + cc;
            *(float2*)&Dm[o0] = v0;
            *(float2*)&Dm[o1] = v1;
            if (Eh) { emit_pair(Eh, El, o0, v0); emit_pair(Eh, El, o1, v1); }
            if (Fh) {
                float2 w0 = v0, w1 = v1;
                if (r0 == cc)     w0.x += 1.0f;
                if (r0 == cc + 1) w0.y += 1.0f;
                if (r1 == cc)     w1.x += 1.0f;
                if (r1 == cc + 1) w1.y += 1.0f;
                emit_pair(Fh, Fl, o0, w0); emit_pair(Fh, Fl, o1, w1);
            }
        }
    }
}

// ---------------------------------------------------------------------------
// Fused sigma + z:
//   sigma = mu + eps*exp(logstd)  (computed per batch tile, written to out)
//   z[b]  = S[idx[b],:][:,idx[b]] @ sigma[b]
// Gather uses explicit 8-wide load batches for MLP.
// ---------------------------------------------------------------------------
#define ZSMEM ((NPER * NPER + NPER * DDIM + NPER) * 4)
__global__ void __launch_bounds__(256) z_kernel(
    const float* __restrict__ S,
    const float4* __restrict__ mu, const float4* __restrict__ ls,
    const float4* __restrict__ ep,
    const int* __restrict__ ridx,
    float4* __restrict__ out_sigma, float* __restrict__ z) {
    extern __shared__ float zsm[];
    float* sub_s = zsm;
    float* sig_s = zsm + NPER * NPER;
    int*   rows  = (int*)(sig_s + NPER * DDIM);

    const int b = blockIdx.x;
    const int t = threadIdx.x;

    if (t < NPER) rows[t] = ridx[b * NPER + t];
    {
        const size_t base = (size_t)b * (NPER * DDIM / 4);
        float4* ss = (float4*)sig_s;
        for (int i = t; i < NPER * DDIM / 4; i += 256) {
            float4 m = mu[base + i], l = ls[base + i], e = ep[base + i];
            float4 r;
            r.x = m.x + e.x * expf(l.x);
            r.y = m.y + e.y * expf(l.y);
            r.z = m.z + e.z * expf(l.z);
            r.w = m.w + e.w * expf(l.w);
            ss[i] = r;
            out_sigma[base + i] = r;
        }
    }
    __syncthreads();
    {
        const int tj  = t & 127;
        const int ti0 = (t >> 7) * 64;
        const int cj  = rows[tj];
#pragma unroll
        for (int gblk = 0; gblk < 8; gblk++) {
            float vals[8];
#pragma unroll
            for (int u = 0; u < 8; u++)
                vals[u] = S[(size_t)rows[ti0 + gblk * 8 + u] * MSZ + cj];
#pragma unroll
            for (int u = 0; u < 8; u++)
                sub_s[(ti0 + gblk * 8 + u) * NPER + tj] = vals[u];
        }
    }
    __syncthreads();

    const int d4 = t & 15;
    const int ig = t >> 4;
    unsigned long long accA[8], accB[8];
#pragma unroll
    for (int r = 0; r < 8; r++) { accA[r] = 0ull; accB[r] = 0ull; }

    const float4* sig4 = (const float4*)sig_s;
    for (int j = 0; j < NPER; j++) {
        float4 sv = sig4[j * (DDIM / 4) + d4];
        unsigned long long sxy = pack2(sv.x, sv.y);
        unsigned long long szw = pack2(sv.z, sv.w);
#pragma unroll
        for (int r = 0; r < 8; r++) {
            float a = sub_s[(ig * 8 + r) * NPER + j];
            unsigned long long aa = pack2(a, a);
            fma2(accA[r], aa, sxy);
            fma2(accB[r], aa, szw);
        }
    }
    float4* zp = (float4*)(z + (size_t)b * NPER * DDIM);
#pragma unroll
    for (int r = 0; r < 8; r++) {
        float4 v;
        unpack2(accA[r], v.x, v.y);
        unpack2(accB[r], v.z, v.w);
        zp[(ig * 8 + r) * (DDIM / 4) + d4] = v;
    }
}

// ---------------------------------------------------------------------------
// kernel_launch — order-16 Neumann: S = (I+X)(I+X2)(I+X4)(I+X8)
// ---------------------------------------------------------------------------
extern "C" void kernel_launch(void* const* d_in, const int* in_sizes, int n_in,
                              void* d_out, int out_size) {
    const float* A      = (const float*)d_in[0];
    const float* mu     = (const float*)d_in[1];
    const float* logstd = (const float*)d_in[2];
    const float* eps    = (const float*)d_in[3];
    const void*  nidx   = d_in[4];

    float* out_sigma = (float*)d_out;
    float* out_z     = out_sigma + SIGN;

    float* bufs = nullptr;
    cudaGetSymbolAddress((void**)&bufs, g_scratch);
    __half* hfb = nullptr;
    cudaGetSymbolAddress((void**)&hfb, g_hf);
    int* rows_dev = nullptr;
    cudaGetSymbolAddress((void**)&rows_dev, g_rows);

    float* BX   = bufs + 0 * M2;  // X
    float* BX2  = bufs + 1 * M2;  // X2 -> Q2
    float* BX4  = bufs + 2 * M2;  // X4
    float* BX8  = bufs + 3 * M2;  // X8
    float* BQ1  = bufs + 5 * M2;  // Q1 -> S

    auto P = [&](int p, int hl) { return hfb + ((size_t)(p * 2 + hl)) * M2; };
    __half* NUL = nullptr;

    dim3 gT(MSZ / 32, MSZ / 32), bT(32, 8);
    dim3 gG(MSZ / 64, MSZ / 64);    // (16, 16) = 256 CTAs

    cudaFuncSetAttribute(gemm_h_kernel, cudaFuncAttributeMaxDynamicSharedMemorySize, GSMT);
    cudaFuncSetAttribute(z_kernel, cudaFuncAttributeMaxDynamicSharedMemorySize, ZSMEM);

    idx_detect_kernel<<<1, 256>>>((const unsigned int*)nidx);
    idx_convert_kernel<<<NIDX / 256, 256>>>(nidx);

#define GEMM_T(pa, pb, Cp, Dp, ns, ai, pe, pf) \
    gemm_h_kernel<<<gG, 128, GSMT>>>(P(pa,0), P(pa,1), P(pb,0), P(pb,1), Cp, Dp, ns, ai, \
        (pe) < 0 ? NUL : P(pe,0), (pe) < 0 ? NUL : P(pe,1), \
        (pf) < 0 ? NUL : P(pf,0), (pf) < 0 ? NUL : P(pf,1))

    // pairs: 0=X 1=P1 2=X2 3=X4 4=P4 5=Q1 6=X8 7=Q2
    transpose_cvt_kernel<<<gT, bT>>>(A, BX, P(0,0), P(0,1), P(1,0), P(1,1));
    GEMM_T(0, 0, (const float*)nullptr, BX2, 1, 0, 2, -1);  // X2 = X*X, emit X2
    GEMM_T(2, 2, (const float*)nullptr, BX4, 1, 0, 3, 4);   // X4 = X2*X2, emit X4 + P4
    GEMM_T(1, 2, BX, BQ1, 1, 1, 5, -1);                     // Q1 = P1*X2 + X + I, emit Q1
    GEMM_T(3, 3, (const float*)nullptr, BX8, 1, 0, 6, -1);  // X8 = X4*X4, emit X8
    GEMM_T(4, 6, BX4, BX2, 1, 1, 7, -1);                    // Q2 = P4*X8 + X4 + I, emit Q2
    GEMM_T(5, 7, (const float*)nullptr, BQ1, 3, 0, -1, -1); // S = Q1*Q2 (SPLIT)

    z_kernel<<<NBAT, 256, ZSMEM>>>(BQ1, (const float4*)mu, (const float4*)logstd,
                                   (const float4*)eps, rows_dev,
                                   (float4*)out_sigma, out_z);
#undef GEMM_T
}

// round 11
// speedup vs baseline: 2.8333x; 1.0001x over previous
#include <cuda_runtime.h>
#include <cuda_bf16.h>
#include <cuda_fp16.h>
#include <math.h>
#include <stdint.h>

#define MSZ   1024
#define M2    (MSZ * MSZ)
#define NPER  128
#define DDIM  64
#define NBAT  2048
#define NIDX  (NBAT * NPER)          // 262144
#define SIGN  (NBAT * NPER * DDIM)   // 16777216

// f32 scratch (6 x 4MB) + f16 planes (8 pairs hi/lo = 16 planes x 2MB)
__device__ float g_scratch[6 * M2];
__device__ __half g_hf[16 * M2];
__device__ int g_rows[NIDX];
__device__ unsigned int g_odd_or;

__device__ __forceinline__ uint32_t smem_u32(const void* p) {
    uint32_t a;
    asm("{ .reg .u64 t; cvta.to.shared.u64 t, %1; cvt.u32.u64 %0, t; }" : "=r"(a) : "l"(p));
    return a;
}
// f32x2 packed helpers
__device__ __forceinline__ unsigned long long pack2(float x, float y) {
    unsigned long long r;
    asm("mov.b64 %0, {%1, %2};" : "=l"(r) : "f"(x), "f"(y));
    return r;
}
__device__ __forceinline__ void fma2(unsigned long long& d,
                                     unsigned long long a, unsigned long long b) {
    asm("fma.rn.f32x2 %0, %1, %2, %0;" : "+l"(d) : "l"(a), "l"(b));
}
__device__ __forceinline__ void unpack2(unsigned long long v, float& lo, float& hi) {
    asm("mov.b64 {%0, %1}, %2;" : "=f"(lo), "=f"(hi) : "l"(v));
}
// cp.async
#define CP16(dst, src) \
    asm volatile("cp.async.cg.shared.global [%0], [%1], 16;" :: "r"(dst), "l"(src))
#define CPCOMMIT() asm volatile("cp.async.commit_group;" ::: "memory")
#define CPWAIT2()  asm volatile("cp.async.wait_group 2;" ::: "memory")

// ---------------------------------------------------------------------------
// Index dtype detection + conversion (int64 vs int32 harness layout)
// ---------------------------------------------------------------------------
__global__ void idx_detect_kernel(const unsigned int* __restrict__ v32) {
    __shared__ unsigned int s[256];
    unsigned int o = 0;
    for (int i = threadIdx.x; i < NIDX / 2; i += 256) o |= v32[2 * i + 1];
    s[threadIdx.x] = o;
    __syncthreads();
    for (int d = 128; d > 0; d >>= 1) {
        if (threadIdx.x < d) s[threadIdx.x] |= s[threadIdx.x + d];
        __syncthreads();
    }
    if (threadIdx.x == 0) g_odd_or = s[0];
}
__global__ void idx_convert_kernel(const void* __restrict__ raw) {
    int i = blockIdx.x * blockDim.x + threadIdx.x;
    if (i >= NIDX) return;
    g_rows[i] = (g_odd_or == 0u) ? (int)((const long long*)raw)[i]
                                 : ((const int*)raw)[i];
}

// ---------------------------------------------------------------------------
// Transpose + split: T = A^T (f32), plus f16 planes of X and of P1 = I+X
// ---------------------------------------------------------------------------
__global__ void transpose_cvt_kernel(const float* __restrict__ A, float* __restrict__ T,
                                     __half* __restrict__ xh, __half* __restrict__ xl,
                                     __half* __restrict__ ph, __half* __restrict__ pl) {
    __shared__ float tile[32][33];
    int x = blockIdx.x * 32 + threadIdx.x;
    int y = blockIdx.y * 32 + threadIdx.y;
#pragma unroll
    for (int j = 0; j < 32; j += 8)
        tile[threadIdx.y + j][threadIdx.x] = A[(y + j) * MSZ + x];
    __syncthreads();
    int xT = blockIdx.y * 32 + threadIdx.x;
    int yT0 = blockIdx.x * 32 + threadIdx.y;
#pragma unroll
    for (int j = 0; j < 32; j += 8) {
        int yT = yT0 + j;
        float v = tile[threadIdx.x][threadIdx.y + j];
        size_t o = (size_t)yT * MSZ + xT;
        T[o] = v;
        __half h = __float2half_rn(v);
        xh[o] = h;
        xl[o] = __float2half_rn(v - __half2float(h));
        float w = v + ((yT == xT) ? 1.0f : 0.0f);
        __half hw = __float2half_rn(w);
        ph[o] = hw;
        pl[o] = __float2half_rn(w - __half2float(hw));
    }
}

// ---------------------------------------------------------------------------
// Tensor-core f16 GEMM via mma.sync, cp.async 4-stage pipeline.
//   nseg=1: D = Ah*Bh (+C) (+I);  nseg=3: + Al*Bh + Ah*Bl
// A planes row-major [m][k]; B planes row-major [k][n] (ldmatrix.trans).
// CTA tile 64x64, BK=64, 4 warps (2m x 2n), warp tile 32x32.
// ---------------------------------------------------------------------------
#define ROWB 144
#define ASTG (64 * ROWB)
#define STG  (2 * ASTG)          // A + B per stage = 18432
#define NSTAGE 4
#define GSMT (NSTAGE * STG)      // 73728

__device__ __forceinline__ void ldmx4(uint32_t* r, uint32_t addr) {
    asm volatile("ldmatrix.sync.aligned.m8n8.x4.shared.b16 {%0,%1,%2,%3}, [%4];"
                 : "=r"(r[0]), "=r"(r[1]), "=r"(r[2]), "=r"(r[3]) : "r"(addr));
}
__device__ __forceinline__ void ldmx4t(uint32_t* r, uint32_t addr) {
    asm volatile("ldmatrix.sync.aligned.m8n8.x4.trans.shared.b16 {%0,%1,%2,%3}, [%4];"
                 : "=r"(r[0]), "=r"(r[1]), "=r"(r[2]), "=r"(r[3]) : "r"(addr));
}
__device__ __forceinline__ void mma16816(float* c, const uint32_t* a,
                                         uint32_t b0, uint32_t b1) {
    asm volatile(
        "mma.sync.aligned.m16n8k16.row.col.f32.f16.f16.f32 "
        "{%0,%1,%2,%3}, {%4,%5,%6,%7}, {%8,%9}, {%0,%1,%2,%3};"
        : "+f"(c[0]), "+f"(c[1]), "+f"(c[2]), "+f"(c[3])
        : "r"(a[0]), "r"(a[1]), "r"(a[2]), "r"(a[3]), "r"(b0), "r"(b1));
}
__device__ __forceinline__ void emit_pair(__half* __restrict__ H, __half* __restrict__ L,
                                          size_t o, float2 v) {
    __half2 h = __floats2half2_rn(v.x, v.y);
    *(__half2*)&H[o] = h;
    float2 r = make_float2(v.x - __half2float(__low2half(h)),
                           v.y - __half2float(__high2half(h)));
    *(__half2*)&L[o] = __floats2half2_rn(r.x, r.y);
}

__global__ void __launch_bounds__(128) gemm_h_kernel(
    const __half* __restrict__ Ah, const __half* __restrict__ Al,
    const __half* __restrict__ Bh, const __half* __restrict__ Bl,
    const float* __restrict__ Cm, float* __restrict__ Dm, int nseg, int addI,
    __half* __restrict__ Eh, __half* __restrict__ El,
    __half* __restrict__ Fh, __half* __restrict__ Fl) {
    extern __shared__ char smem[];
    const int t = threadIdx.x;
    const int wid = t >> 5, lid = t & 31;
    const int m0 = blockIdx.y * 64, n0 = blockIdx.x * 64;
    const int wm = wid >> 1, wn = wid & 1;
    const int CMAX = nseg << 4;

    const __half* segA[3] = { Ah, Al, Ah };
    const __half* segB[3] = { Bh, Bh, Bl };

    const int lrow = (lid & 7) + ((lid >> 3) & 1) * 8;  // A-frag row sel
    const int lkof = (lid >> 4) * 8;                    // A-frag k sel
    const int bkr  = lid & 15;                          // B-frag k row
    const int bnof = (lid >> 4) * 8;                    // B-frag n sel

    // per-thread load mapping (4 x (A row + B row) per chunk)
    const int lr = t >> 3, lq = t & 7;

    float acc[2][4][4];
#pragma unroll
    for (int i = 0; i < 2; i++)
#pragma unroll
        for (int j = 0; j < 4; j++)
#pragma unroll
            for (int e = 0; e < 4; e++) acc[i][j][e] = 0.0f;

    const uint32_t sbase = smem_u32(smem);

    // issue chunk `cn` into stage `st`
    auto load_chunk = [&](int cn, int st) {
        const __half* Ap = segA[cn >> 4];
        const __half* Bp = segB[cn >> 4];
        const int k0 = (cn & 15) * 64;
        const uint32_t sa = sbase + st * STG;
        const uint32_t sb = sa + ASTG;
#pragma unroll
        for (int i = 0; i < 4; i++) {
            int r = lr + 16 * i;
            uint32_t so = (uint32_t)(r * ROWB + lq * 16);
            CP16(sa + so, Ap + (size_t)(m0 + r) * MSZ + k0 + lq * 8);
            CP16(sb + so, Bp + (size_t)(k0 + r) * MSZ + n0 + lq * 8);
        }
        CPCOMMIT();
    };

    // preload 3 chunks
    load_chunk(0, 0);
    load_chunk(1, 1);
    load_chunk(2, 2);

    for (int c = 0; c < CMAX; c++) {
        CPWAIT2();              // chunk c's group complete (3-deep in flight)
        __syncthreads();        // all threads' stage data visible; prev stage free

        // keep 3 groups in flight (empty commits during drain keep count exact)
        if (c + 3 < CMAX) load_chunk(c + 3, (c + 3) & (NSTAGE - 1));
        else CPCOMMIT();

        const uint32_t sa = sbase + (c & (NSTAGE - 1)) * STG;
        const uint32_t sb = sa + ASTG;
#pragma unroll
        for (int ks = 0; ks < 4; ks++) {
            uint32_t af[2][4], bf[2][4];
#pragma unroll
            for (int i = 0; i < 2; i++)
                ldmx4(af[i], sa + (uint32_t)((wm * 32 + i * 16 + lrow) * ROWB +
                                             (ks * 16 + lkof) * 2));
#pragma unroll
            for (int j2 = 0; j2 < 2; j2++)
                ldmx4t(bf[j2], sb + (uint32_t)((ks * 16 + bkr) * ROWB +
                                               (wn * 32 + j2 * 16 + bnof) * 2));
#pragma unroll
            for (int i = 0; i < 2; i++)
#pragma unroll
                for (int j = 0; j < 4; j++)
                    mma16816(acc[i][j], af[i], bf[j >> 1][2 * (j & 1)],
                             bf[j >> 1][2 * (j & 1) + 1]);
        }
        __syncthreads();        // stage reusable only after every warp computed
    }

    const int g = lid >> 2, q = lid & 3;
#pragma unroll
    for (int i = 0; i < 2; i++) {
#pragma unroll
        for (int j = 0; j < 4; j++) {
            int r0 = m0 + wm * 32 + i * 16 + g;
            int r1 = r0 + 8;
            int cc = n0 + wn * 32 + j * 8 + q * 2;
            float2 v0 = make_float2(acc[i][j][0], acc[i][j][1]);
            float2 v1 = make_float2(acc[i][j][2], acc[i][j][3]);
            if (Cm) {
                float2 c0 = *(const float2*)&Cm[(size_t)r0 * MSZ + cc];
                float2 c1 = *(const float2*)&Cm[(size_t)r1 * MSZ + cc];
                v0.x += c0.x; v0.y += c0.y;
                v1.x += c1.x; v1.y += c1.y;
            }
            if (addI) {
                if (r0 == cc)     v0.x += 1.0f;
                if (r0 == cc + 1) v0.y += 1.0f;
                if (r1 == cc)     v1.x += 1.0f;
                if (r1 == cc + 1) v1.y += 1.0f;
            }
            size_t o0 = (size_t)r0 * MSZ + cc, o1 = (size_t)r1 * MSZ + cc;
            *(float2*)&Dm[o0] = v0;
            *(float2*)&Dm[o1] = v1;
            if (Eh) { emit_pair(Eh, El, o0, v0); emit_pair(Eh, El, o1, v1); }
            if (Fh) {
                float2 w0 = v0, w1 = v1;
                if (r0 == cc)     w0.x += 1.0f;
                if (r0 == cc + 1) w0.y += 1.0f;
                if (r1 == cc)     w1.x += 1.0f;
                if (r1 == cc + 1) w1.y += 1.0f;
                emit_pair(Fh, Fl, o0, w0); emit_pair(Fh, Fl, o1, w1);
            }
        }
    }
}

// ---------------------------------------------------------------------------
// Fused sigma + z:
//   sigma = mu + eps*exp(logstd)  (computed per batch tile, written to out)
//   z[b]  = S[idx[b],:][:,idx[b]] @ sigma[b]
// ---------------------------------------------------------------------------
#define ZSMEM ((NPER * NPER + NPER * DDIM + NPER) * 4)
__global__ void __launch_bounds__(256) z_kernel(
    const float* __restrict__ S,
    const float4* __restrict__ mu, const float4* __restrict__ ls,
    const float4* __restrict__ ep,
    const int* __restrict__ ridx,
    float4* __restrict__ out_sigma, float* __restrict__ z) {
    extern __shared__ float zsm[];
    float* sub_s = zsm;
    float* sig_s = zsm + NPER * NPER;
    int*   rows  = (int*)(sig_s + NPER * DDIM);

    const int b = blockIdx.x;
    const int t = threadIdx.x;

    if (t < NPER) rows[t] = ridx[b * NPER + t];
    {
        const size_t base = (size_t)b * (NPER * DDIM / 4);
        float4* ss = (float4*)sig_s;
        for (int i = t; i < NPER * DDIM / 4; i += 256) {
            float4 m = mu[base + i], l = ls[base + i], e = ep[base + i];
            float4 r;
            r.x = m.x + e.x * expf(l.x);
            r.y = m.y + e.y * expf(l.y);
            r.z = m.z + e.z * expf(l.z);
            r.w = m.w + e.w * expf(l.w);
            ss[i] = r;
            out_sigma[base + i] = r;
        }
    }
    __syncthreads();
    {
        const int tj  = t & 127;
        const int ti0 = (t >> 7) * 64;
        const int cj  = rows[tj];
#pragma unroll
        for (int gblk = 0; gblk < 8; gblk++) {
            float vals[8];
#pragma unroll
            for (int u = 0; u < 8; u++)
                vals[u] = S[(size_t)rows[ti0 + gblk * 8 + u] * MSZ + cj];
#pragma unroll
            for (int u = 0; u < 8; u++)
                sub_s[(ti0 + gblk * 8 + u) * NPER + tj] = vals[u];
        }
    }
    __syncthreads();

    const int d4 = t & 15;
    const int ig = t >> 4;
    unsigned long long accA[8], accB[8];
#pragma unroll
    for (int r = 0; r < 8; r++) { accA[r] = 0ull; accB[r] = 0ull; }

    const float4* sig4 = (const float4*)sig_s;
    for (int j = 0; j < NPER; j++) {
        float4 sv = sig4[j * (DDIM / 4) + d4];
        unsigned long long sxy = pack2(sv.x, sv.y);
        unsigned long long szw = pack2(sv.z, sv.w);
#pragma unroll
        for (int r = 0; r < 8; r++) {
            float a = sub_s[(ig * 8 + r) * NPER + j];
            unsigned long long aa = pack2(a, a);
            fma2(accA[r], aa, sxy);
            fma2(accB[r], aa, szw);
        }
    }
    float4* zp = (float4*)(z + (size_t)b * NPER * DDIM);
#pragma unroll
    for (int r = 0; r < 8; r++) {
        float4 v;
        unpack2(accA[r], v.x, v.y);
        unpack2(accB[r], v.z, v.w);
        zp[(ig * 8 + r) * (DDIM / 4) + d4] = v;
    }
}

// ---------------------------------------------------------------------------
// kernel_launch — order-16 Neumann: S = (I+X)(I+X2)(I+X4)(I+X8)
// ---------------------------------------------------------------------------
extern "C" void kernel_launch(void* const* d_in, const int* in_sizes, int n_in,
                              void* d_out, int out_size) {
    const float* A      = (const float*)d_in[0];
    const float* mu     = (const float*)d_in[1];
    const float* logstd = (const float*)d_in[2];
    const float* eps    = (const float*)d_in[3];
    const void*  nidx   = d_in[4];

    float* out_sigma = (float*)d_out;
    float* out_z     = out_sigma + SIGN;

    float* bufs = nullptr;
    cudaGetSymbolAddress((void**)&bufs, g_scratch);
    __half* hfb = nullptr;
    cudaGetSymbolAddress((void**)&hfb, g_hf);
    int* rows_dev = nullptr;
    cudaGetSymbolAddress((void**)&rows_dev, g_rows);

    float* BX   = bufs + 0 * M2;  // X
    float* BX2  = bufs + 1 * M2;  // X2 -> Q2
    float* BX4  = bufs + 2 * M2;  // X4
    float* BX8  = bufs + 3 * M2;  // X8
    float* BQ1  = bufs + 5 * M2;  // Q1 -> S

    auto P = [&](int p, int hl) { return hfb + ((size_t)(p * 2 + hl)) * M2; };
    __half* NUL = nullptr;

    dim3 gT(MSZ / 32, MSZ / 32), bT(32, 8);
    dim3 gG(MSZ / 64, MSZ / 64);    // (16, 16) = 256 CTAs

    cudaFuncSetAttribute(gemm_h_kernel, cudaFuncAttributeMaxDynamicSharedMemorySize, GSMT);
    cudaFuncSetAttribute(z_kernel, cudaFuncAttributeMaxDynamicSharedMemorySize, ZSMEM);

    idx_detect_kernel<<<1, 256>>>((const unsigned int*)nidx);
    idx_convert_kernel<<<NIDX / 256, 256>>>(nidx);

#define GEMM_T(pa, pb, Cp, Dp, ns, ai, pe, pf) \
    gemm_h_kernel<<<gG, 128, GSMT>>>(P(pa,0), P(pa,1), P(pb,0), P(pb,1), Cp, Dp, ns, ai, \
        (pe) < 0 ? NUL : P(pe,0), (pe) < 0 ? NUL : P(pe,1), \
        (pf) < 0 ? NUL : P(pf,0), (pf) < 0 ? NUL : P(pf,1))

    // pairs: 0=X 1=P1 2=X2 3=X4 4=P4 5=Q1 6=X8 7=Q2
    transpose_cvt_kernel<<<gT, bT>>>(A, BX, P(0,0), P(0,1), P(1,0), P(1,1));
    GEMM_T(0, 0, (const float*)nullptr, BX2, 1, 0, 2, -1);  // X2 = X*X, emit X2
    GEMM_T(2, 2, (const float*)nullptr, BX4, 1, 0, 3, 4);   // X4 = X2*X2, emit X4 + P4
    GEMM_T(1, 2, BX, BQ1, 1, 1, 5, -1);                     // Q1 = P1*X2 + X + I, emit Q1
    GEMM_T(3, 3, (const float*)nullptr, BX8, 1, 0, 6, -1);  // X8 = X4*X4, emit X8
    GEMM_T(4, 6, BX4, BX2, 1, 1, 7, -1);                    // Q2 = P4*X8 + X4 + I, emit Q2
    GEMM_T(5, 7, (const float*)nullptr, BQ1, 3, 0, -1, -1); // S = Q1*Q2 (SPLIT)

    z_kernel<<<NBAT, 256, ZSMEM>>>(BQ1, (const float4*)mu, (const float4*)logstd,
                                   (const float4*)eps, rows_dev,
                                   (float4*)out_sigma, out_z);
#undef GEMM_T
}

// round 14
// speedup vs baseline: 3.2569x; 1.1495x over previous
#include <cuda_runtime.h>
#include <cuda_bf16.h>
#include <cuda_fp16.h>
#include <math.h>
#include <stdint.h>

#define MSZ   1024
#define M2    (MSZ * MSZ)
#define NPER  128
#define DDIM  64
#define NBAT  2048
#define NIDX  (NBAT * NPER)          // 262144
#define SIGN  (NBAT * NPER * DDIM)   // 16777216

// f32 scratch (6 x 4MB) + f16 planes (8 pairs hi/lo = 16 planes x 2MB)
__device__ float g_scratch[6 * M2];
__device__ __half g_hf[16 * M2];
__device__ int g_rows[NIDX];
__device__ unsigned int g_odd_or;

__device__ __forceinline__ uint32_t smem_u32(const void* p) {
    uint32_t a;
    asm("{ .reg .u64 t; cvta.to.shared.u64 t, %1; cvt.u32.u64 %0, t; }" : "=r"(a) : "l"(p));
    return a;
}
// f32x2 packed helpers
__device__ __forceinline__ unsigned long long pack2(float x, float y) {
    unsigned long long r;
    asm("mov.b64 %0, {%1, %2};" : "=l"(r) : "f"(x), "f"(y));
    return r;
}
__device__ __forceinline__ void fma2(unsigned long long& d,
                                     unsigned long long a, unsigned long long b) {
    asm("fma.rn.f32x2 %0, %1, %2, %0;" : "+l"(d) : "l"(a), "l"(b));
}
__device__ __forceinline__ void unpack2(unsigned long long v, float& lo, float& hi) {
    asm("mov.b64 {%0, %1}, %2;" : "=f"(lo), "=f"(hi) : "l"(v));
}
// cp.async
#define CP16(dst, src) \
    asm volatile("cp.async.cg.shared.global [%0], [%1], 16;" :: "r"(dst), "l"(src))
#define CPCOMMIT() asm volatile("cp.async.commit_group;" ::: "memory")
#define CPWAIT2()  asm volatile("cp.async.wait_group 2;" ::: "memory")

// ---------------------------------------------------------------------------
// Index dtype detection + conversion (int64 vs int32 harness layout)
// ---------------------------------------------------------------------------
__global__ void idx_detect_kernel(const unsigned int* __restrict__ v32) {
    __shared__ unsigned int s[256];
    unsigned int o = 0;
    for (int i = threadIdx.x; i < NIDX / 2; i += 256) o |= v32[2 * i + 1];
    s[threadIdx.x] = o;
    __syncthreads();
    for (int d = 128; d > 0; d >>= 1) {
        if (threadIdx.x < d) s[threadIdx.x] |= s[threadIdx.x + d];
        __syncthreads();
    }
    if (threadIdx.x == 0) g_odd_or = s[0];
}
__global__ void idx_convert_kernel(const void* __restrict__ raw) {
    int i = blockIdx.x * blockDim.x + threadIdx.x;
    if (i >= NIDX) return;
    g_rows[i] = (g_odd_or == 0u) ? (int)((const long long*)raw)[i]
                                 : ((const int*)raw)[i];
}

// ---------------------------------------------------------------------------
// Transpose + split: T = A^T (f32), plus f16 planes of X and of P1 = I+X
// ---------------------------------------------------------------------------
__global__ void transpose_cvt_kernel(const float* __restrict__ A, float* __restrict__ T,
                                     __half* __restrict__ xh, __half* __restrict__ xl,
                                     __half* __restrict__ ph, __half* __restrict__ pl) {
    __shared__ float tile[32][33];
    int x = blockIdx.x * 32 + threadIdx.x;
    int y = blockIdx.y * 32 + threadIdx.y;
#pragma unroll
    for (int j = 0; j < 32; j += 8)
        tile[threadIdx.y + j][threadIdx.x] = A[(y + j) * MSZ + x];
    __syncthreads();
    int xT = blockIdx.y * 32 + threadIdx.x;
    int yT0 = blockIdx.x * 32 + threadIdx.y;
#pragma unroll
    for (int j = 0; j < 32; j += 8) {
        int yT = yT0 + j;
        float v = tile[threadIdx.x][threadIdx.y + j];
        size_t o = (size_t)yT * MSZ + xT;
        T[o] = v;
        __half h = __float2half_rn(v);
        xh[o] = h;
        xl[o] = __float2half_rn(v - __half2float(h));
        float w = v + ((yT == xT) ? 1.0f : 0.0f);
        __half hw = __float2half_rn(w);
        ph[o] = hw;
        pl[o] = __float2half_rn(w - __half2float(hw));
    }
}

// ---------------------------------------------------------------------------
// Tensor-core f16 GEMM via mma.sync, cp.async 4-stage pipeline.
//   nseg=1: D = Ah*Bh (+C) (+I)
//   nseg=2: D = Ah*Bh + Al*Bh (+C) (+I)   [A split only]
//   nseg=3: D = Ah*Bh + Al*Bh + Ah*Bl (+C) (+I)
// A planes row-major [m][k]; B planes row-major [k][n] (ldmatrix.trans).
// CTA tile 64x64, BK=64, 4 warps (2m x 2n), warp tile 32x32.
// ---------------------------------------------------------------------------
#define ROWB 144
#define ASTG (64 * ROWB)
#define STG  (2 * ASTG)          // A + B per stage = 18432
#define NSTAGE 4
#define GSMT (NSTAGE * STG)      // 73728

__device__ __forceinline__ void ldmx4(uint32_t* r, uint32_t addr) {
    asm volatile("ldmatrix.sync.aligned.m8n8.x4.shared.b16 {%0,%1,%2,%3}, [%4];"
                 : "=r"(r[0]), "=r"(r[1]), "=r"(r[2]), "=r"(r[3]) : "r"(addr));
}
__device__ __forceinline__ void ldmx4t(uint32_t* r, uint32_t addr) {
    asm volatile("ldmatrix.sync.aligned.m8n8.x4.trans.shared.b16 {%0,%1,%2,%3}, [%4];"
                 : "=r"(r[0]), "=r"(r[1]), "=r"(r[2]), "=r"(r[3]) : "r"(addr));
}
__device__ __forceinline__ void mma16816(float* c, const uint32_t* a,
                                         uint32_t b0, uint32_t b1) {
    asm volatile(
        "mma.sync.aligned.m16n8k16.row.col.f32.f16.f16.f32 "
        "{%0,%1,%2,%3}, {%4,%5,%6,%7}, {%8,%9}, {%0,%1,%2,%3};"
        : "+f"(c[0]), "+f"(c[1]), "+f"(c[2]), "+f"(c[3])
        : "r"(a[0]), "r"(a[1]), "r"(a[2]), "r"(a[3]), "r"(b0), "r"(b1));
}
__device__ __forceinline__ void emit_pair(__half* __restrict__ H, __half* __restrict__ L,
                                          size_t o, float2 v) {
    __half2 h = __floats2half2_rn(v.x, v.y);
    *(__half2*)&H[o] = h;
    float2 r = make_float2(v.x - __half2float(__low2half(h)),
                           v.y - __half2float(__high2half(h)));
    *(__half2*)&L[o] = __floats2half2_rn(r.x, r.y);
}

__global__ void __launch_bounds__(128) gemm_h_kernel(
    const __half* __restrict__ Ah, const __half* __restrict__ Al,
    const __half* __restrict__ Bh, const __half* __restrict__ Bl,
    const float* __restrict__ Cm, float* __restrict__ Dm, int nseg, int addI,
    __half* __restrict__ Eh, __half* __restrict__ El,
    __half* __restrict__ Fh, __half* __restrict__ Fl) {
    extern __shared__ char smem[];
    const int t = threadIdx.x;
    const int wid = t >> 5, lid = t & 31;
    const int m0 = blockIdx.y * 64, n0 = blockIdx.x * 64;
    const int wm = wid >> 1, wn = wid & 1;
    const int CMAX = nseg << 4;

    const __half* segA[3] = { Ah, Al, Ah };
    const __half* segB[3] = { Bh, Bh, Bl };

    const int lrow = (lid & 7) + ((lid >> 3) & 1) * 8;  // A-frag row sel
    const int lkof = (lid >> 4) * 8;                    // A-frag k sel
    const int bkr  = lid & 15;                          // B-frag k row
    const int bnof = (lid >> 4) * 8;                    // B-frag n sel

    const int lr = t >> 3, lq = t & 7;

    float acc[2][4][4];
#pragma unroll
    for (int i = 0; i < 2; i++)
#pragma unroll
        for (int j = 0; j < 4; j++)
#pragma unroll
            for (int e = 0; e < 4; e++) acc[i][j][e] = 0.0f;

    const uint32_t sbase = smem_u32(smem);

    auto load_chunk = [&](int cn, int st) {
        const __half* Ap = segA[cn >> 4];
        const __half* Bp = segB[cn >> 4];
        const int k0 = (cn & 15) * 64;
        const uint32_t sa = sbase + st * STG;
        const uint32_t sb = sa + ASTG;
#pragma unroll
        for (int i = 0; i < 4; i++) {
            int r = lr + 16 * i;
            uint32_t so = (uint32_t)(r * ROWB + lq * 16);
            CP16(sa + so, Ap + (size_t)(m0 + r) * MSZ + k0 + lq * 8);
            CP16(sb + so, Bp + (size_t)(k0 + r) * MSZ + n0 + lq * 8);
        }
        CPCOMMIT();
    };

    load_chunk(0, 0);
    load_chunk(1, 1);
    load_chunk(2, 2);

    for (int c = 0; c < CMAX; c++) {
        CPWAIT2();
        __syncthreads();

        if (c + 3 < CMAX) load_chunk(c + 3, (c + 3) & (NSTAGE - 1));
        else CPCOMMIT();

        const uint32_t sa = sbase + (c & (NSTAGE - 1)) * STG;
        const uint32_t sb = sa + ASTG;
#pragma unroll
        for (int ks = 0; ks < 4; ks++) {
            uint32_t af[2][4], bf[2][4];
#pragma unroll
            for (int i = 0; i < 2; i++)
                ldmx4(af[i], sa + (uint32_t)((wm * 32 + i * 16 + lrow) * ROWB +
                                             (ks * 16 + lkof) * 2));
#pragma unroll
            for (int j2 = 0; j2 < 2; j2++)
                ldmx4t(bf[j2], sb + (uint32_t)((ks * 16 + bkr) * ROWB +
                                               (wn * 32 + j2 * 16 + bnof) * 2));
#pragma unroll
            for (int i = 0; i < 2; i++)
#pragma unroll
                for (int j = 0; j < 4; j++)
                    mma16816(acc[i][j], af[i], bf[j >> 1][2 * (j & 1)],
                             bf[j >> 1][2 * (j & 1) + 1]);
        }
        __syncthreads();
    }

    const int g = lid >> 2, q = lid & 3;
#pragma unroll
    for (int i = 0; i < 2; i++) {
#pragma unroll
        for (int j = 0; j < 4; j++) {
            int r0 = m0 + wm * 32 + i * 16 + g;
            int r1 = r0 + 8;
            int cc = n0 + wn * 32 + j * 8 + q * 2;
            float2 v0 = make_float2(acc[i][j][0], acc[i][j][1]);
            float2 v1 = make_float2(acc[i][j][2], acc[i][j][3]);
            if (Cm) {
                float2 c0 = *(const float2*)&Cm[(size_t)r0 * MSZ + cc];
                float2 c1 = *(const float2*)&Cm[(size_t)r1 * MSZ + cc];
                v0.x += c0.x; v0.y += c0.y;
                v1.x += c1.x; v1.y += c1.y;
            }
            if (addI) {
                if (r0 == cc)     v0.x += 1.0f;
                if (r0 == cc + 1) v0.y += 1.0f;
                if (r1 == cc)     v1.x += 1.0f;
                if (r1 == cc + 1) v1.y += 1.0f;
            }
            size_t o0 = (size_t)r0 * MSZ + cc, o1 = (size_t)r1 * MSZ + cc;
            *(float2*)&Dm[o0] = v0;
            *(float2*)&Dm[o1] = v1;
            if (Eh) { emit_pair(Eh, El, o0, v0); emit_pair(Eh, El, o1, v1); }
            if (Fh) {
                float2 w0 = v0, w1 = v1;
                if (r0 == cc)     w0.x += 1.0f;
                if (r0 == cc + 1) w0.y += 1.0f;
                if (r1 == cc)     w1.x += 1.0f;
                if (r1 == cc + 1) w1.y += 1.0f;
                emit_pair(Fh, Fl, o0, w0); emit_pair(Fh, Fl, o1, w1);
            }
        }
    }
}

// ---------------------------------------------------------------------------
// Fused sigma + z:
//   sigma = mu + eps*exp(logstd)  (computed per batch tile, written to out)
//   z[b]  = S[idx[b],:][:,idx[b]] @ sigma[b]
// ---------------------------------------------------------------------------
#define ZSMEM ((NPER * NPER + NPER * DDIM + NPER) * 4)
__global__ void __launch_bounds__(256) z_kernel(
    const float* __restrict__ S,
    const float4* __restrict__ mu, const float4* __restrict__ ls,
    const float4* __restrict__ ep,
    const int* __restrict__ ridx,
    float4* __restrict__ out_sigma, float* __restrict__ z) {
    extern __shared__ float zsm[];
    float* sub_s = zsm;
    float* sig_s = zsm + NPER * NPER;
    int*   rows  = (int*)(sig_s + NPER * DDIM);

    const int b = blockIdx.x;
    const int t = threadIdx.x;

    if (t < NPER) rows[t] = ridx[b * NPER + t];
    {
        const size_t base = (size_t)b * (NPER * DDIM / 4);
        float4* ss = (float4*)sig_s;
        for (int i = t; i < NPER * DDIM / 4; i += 256) {
            float4 m = mu[base + i], l = ls[base + i], e = ep[base + i];
            float4 r;
            r.x = m.x + e.x * expf(l.x);
            r.y = m.y + e.y * expf(l.y);
            r.z = m.z + e.z * expf(l.z);
            r.w = m.w + e.w * expf(l.w);
            ss[i] = r;
            out_sigma[base + i] = r;
        }
    }
    __syncthreads();
    {
        const int tj  = t & 127;
        const int ti0 = (t >> 7) * 64;
        const int cj  = rows[tj];
#pragma unroll
        for (int gblk = 0; gblk < 8; gblk++) {
            float vals[8];
#pragma unroll
            for (int u = 0; u < 8; u++)
                vals[u] = S[(size_t)rows[ti0 + gblk * 8 + u] * MSZ + cj];
#pragma unroll
            for (int u = 0; u < 8; u++)
                sub_s[(ti0 + gblk * 8 + u) * NPER + tj] = vals[u];
        }
    }
    __syncthreads();

    const int d4 = t & 15;
    const int ig = t >> 4;
    unsigned long long accA[8], accB[8];
#pragma unroll
    for (int r = 0; r < 8; r++) { accA[r] = 0ull; accB[r] = 0ull; }

    const float4* sig4 = (const float4*)sig_s;
    for (int j = 0; j < NPER; j++) {
        float4 sv = sig4[j * (DDIM / 4) + d4];
        unsigned long long sxy = pack2(sv.x, sv.y);
        unsigned long long szw = pack2(sv.z, sv.w);
#pragma unroll
        for (int r = 0; r < 8; r++) {
            float a = sub_s[(ig * 8 + r) * NPER + j];
            unsigned long long aa = pack2(a, a);
            fma2(accA[r], aa, sxy);
            fma2(accB[r], aa, szw);
        }
    }
    float4* zp = (float4*)(z + (size_t)b * NPER * DDIM);
#pragma unroll
    for (int r = 0; r < 8; r++) {
        float4 v;
        unpack2(accA[r], v.x, v.y);
        unpack2(accB[r], v.z, v.w);
        zp[(ig * 8 + r) * (DDIM / 4) + d4] = v;
    }
}

// ---------------------------------------------------------------------------
// kernel_launch — order-8 Neumann: S = (I+X)(I+X2)(I+X4) = Q1 * P4
// ---------------------------------------------------------------------------
extern "C" void kernel_launch(void* const* d_in, const int* in_sizes, int n_in,
                              void* d_out, int out_size) {
    const float* A      = (const float*)d_in[0];
    const float* mu     = (const float*)d_in[1];
    const float* logstd = (const float*)d_in[2];
    const float* eps    = (const float*)d_in[3];
    const void*  nidx   = d_in[4];

    float* out_sigma = (float*)d_out;
    float* out_z     = out_sigma + SIGN;

    float* bufs = nullptr;
    cudaGetSymbolAddress((void**)&bufs, g_scratch);
    __half* hfb = nullptr;
    cudaGetSymbolAddress((void**)&hfb, g_hf);
    int* rows_dev = nullptr;
    cudaGetSymbolAddress((void**)&rows_dev, g_rows);

    float* BX   = bufs + 0 * M2;  // X
    float* BX2  = bufs + 1 * M2;  // X2
    float* BX4  = bufs + 2 * M2;  // X4 (f32 unused downstream, scratch sink)
    float* BQ1  = bufs + 5 * M2;  // Q1 -> S

    auto P = [&](int p, int hl) { return hfb + ((size_t)(p * 2 + hl)) * M2; };
    __half* NUL = nullptr;

    dim3 gT(MSZ / 32, MSZ / 32), bT(32, 8);
    dim3 gG(MSZ / 64, MSZ / 64);    // (16, 16) = 256 CTAs

    cudaFuncSetAttribute(gemm_h_kernel, cudaFuncAttributeMaxDynamicSharedMemorySize, GSMT);
    cudaFuncSetAttribute(z_kernel, cudaFuncAttributeMaxDynamicSharedMemorySize, ZSMEM);

    idx_detect_kernel<<<1, 256>>>((const unsigned int*)nidx);
    idx_convert_kernel<<<NIDX / 256, 256>>>(nidx);

#define GEMM_T(pa, pb, Cp, Dp, ns, ai, pe, pf) \
    gemm_h_kernel<<<gG, 128, GSMT>>>(P(pa,0), P(pa,1), P(pb,0), P(pb,1), Cp, Dp, ns, ai, \
        (pe) < 0 ? NUL : P(pe,0), (pe) < 0 ? NUL : P(pe,1), \
        (pf) < 0 ? NUL : P(pf,0), (pf) < 0 ? NUL : P(pf,1))

    // pairs: 0=X 1=P1 2=X2 4=P4 5=Q1
    transpose_cvt_kernel<<<gT, bT>>>(A, BX, P(0,0), P(0,1), P(1,0), P(1,1));
    GEMM_T(0, 0, (const float*)nullptr, BX2, 1, 0, 2, -1);  // X2 = X*X, emit X2
    GEMM_T(2, 2, (const float*)nullptr, BX4, 1, 0, -1, 4);  // X4 = X2*X2, emit P4=I+X4
    GEMM_T(1, 2, BX, BQ1, 1, 1, 5, -1);                     // Q1 = P1*X2 + X + I, emit Q1
    GEMM_T(5, 4, (const float*)nullptr, BQ1, 2, 0, -1, -1); // S = Q1*P4 (A-split, nseg=2)

    z_kernel<<<NBAT, 256, ZSMEM>>>(BQ1, (const float4*)mu, (const float4*)logstd,
                                   (const float4*)eps, rows_dev,
                                   (float4*)out_sigma, out_z);
#undef GEMM_T
}